// round 11
// baseline (speedup 1.0000x reference)
#include <cuda_runtime.h>
#include <cuda_bf16.h>
#include <float.h>
#include <stdint.h>

#define Bsz 16
#define Npt 4096
#define Cft 64
#define Mc  1024
#define Kn  64
#define Hd  128
#define CIN 67

__device__ int   g_idx[Bsz*Mc];
__device__ int   g_prog[Bsz];
__device__ int   g_work;
__device__ float g_poss_dump[Bsz*Mc*3];

// ---------------- acquire/release helpers ---------------------------------
__device__ __forceinline__ int ld_acq(const int* p) {
    int v;
    asm volatile("ld.acquire.gpu.global.b32 %0, [%1];" : "=r"(v) : "l"(p));
    return v;
}
__device__ __forceinline__ void st_rel(int* p, int v) {
    asm volatile("st.release.gpu.global.b32 [%0], %1;" :: "l"(p), "r"(v));
}

// ============================ 1) FPS producer (R9 shape + progress) =======
#define FPS_T 1024
#define FPPT 4
extern __shared__ float fps_sm[];

__global__ __launch_bounds__(FPS_T) void fps_kernel(const float* __restrict__ pos) {
    float* spx = fps_sm;
    float* spy = spx + Npt;
    float* spz = spy + Npt;
    __shared__ unsigned swv[2][32];
    __shared__ unsigned swc[2][32];

    int b = blockIdx.x;
    const float* p = pos + b * Npt * 3;
    int t = threadIdx.x, lane = t & 31, w = t >> 5;

    float px[FPPT], py[FPPT], pz[FPPT], dd[FPPT];
#pragma unroll
    for (int j = 0; j < FPPT; j++) {
        int i = t + j * FPS_T;
        float xx = p[i*3+0], yy = p[i*3+1], zz = p[i*3+2];
        px[j] = xx; py[j] = yy; pz[j] = zz;
        spx[i] = xx; spy[i] = yy; spz[i] = zz;
        dd[j] = FLT_MAX;
    }
    if (t == 0) { g_idx[b * Mc] = 0; st_rel(&g_prog[b], 1); }
    __syncthreads();

    int last = 0, par = 0;
    for (int s = 1; s < Mc; s++) {
        float lx = spx[last], ly = spy[last], lz = spz[last];
        unsigned vmx = 0u;
#pragma unroll
        for (int j = 0; j < FPPT; j++) {
            float dx = __fsub_rn(px[j], lx);
            float dy = __fsub_rn(py[j], ly);
            float dz = __fsub_rn(pz[j], lz);
            float d  = __fadd_rn(__fadd_rn(__fmul_rn(dx,dx), __fmul_rn(dy,dy)),
                                 __fmul_rn(dz,dz));
            float v = fminf(dd[j], d);
            dd[j] = v;
            unsigned vu = __float_as_uint(v);
            vmx = vmx > vu ? vmx : vu;
        }
        unsigned cand = 0x7fffffffu;
#pragma unroll
        for (int j = FPPT - 1; j >= 0; j--)
            if (__float_as_uint(dd[j]) == vmx) cand = (unsigned)(t + j * FPS_T);
        unsigned wmax = __reduce_max_sync(0xffffffffu, vmx);
        unsigned csel = (vmx == wmax) ? cand : 0x7fffffffu;
        unsigned wcnd = __reduce_min_sync(0xffffffffu, csel);
        if (lane == 0) { swv[par][w] = wmax; swc[par][w] = wcnd; }
        __syncthreads();
        unsigned vv = swv[par][lane], cc = swc[par][lane];
        unsigned vm  = __reduce_max_sync(0xffffffffu, vv);
        unsigned cmn = __reduce_min_sync(0xffffffffu, (vv == vm) ? cc : 0x7fffffffu);
        last = (int)cmn;
        par ^= 1;
        if (t == 0) { g_idx[b * Mc + s] = last; st_rel(&g_prog[b], s + 1); }
    }
}

// ============================ 2) consumer: query + MLP (R10 body) =========
#define PITCH 272
#define OFF_W1H 0
#define OFF_W1L 21760
#define OFF_W2H 43520
#define OFF_W2L 78336
#define OFF_FH  113152
#define OFF_FL  147968
#define OFF_B1  182784
#define OFF_B2  183296
#define OFF_WMX 183808
#define MLP_SMEM 187904

__device__ __forceinline__ uint32_t smem_u32(const void* p) {
    uint32_t a;
    asm("{ .reg .u64 t; cvta.to.shared.u64 t, %1; cvt.u32.u64 %0, t; }"
        : "=r"(a) : "l"(p));
    return a;
}
__device__ __forceinline__ void ldsm_x4(uint32_t addr, uint32_t* r) {
    asm volatile("ldmatrix.sync.aligned.m8n8.x4.shared.b16 {%0,%1,%2,%3}, [%4];"
        : "=r"(r[0]), "=r"(r[1]), "=r"(r[2]), "=r"(r[3]) : "r"(addr));
}
__device__ __forceinline__ void ldsm_x4t(uint32_t addr, uint32_t* r) {
    asm volatile("ldmatrix.sync.aligned.m8n8.x4.trans.shared.b16 {%0,%1,%2,%3}, [%4];"
        : "=r"(r[0]), "=r"(r[1]), "=r"(r[2]), "=r"(r[3]) : "r"(addr));
}
__device__ __forceinline__ void mma16816(float* d, const uint32_t* a, const uint32_t* b) {
    asm volatile("mma.sync.aligned.m16n8k16.row.col.f32.bf16.bf16.f32 "
        "{%0,%1,%2,%3}, {%4,%5,%6,%7}, {%8,%9}, {%0,%1,%2,%3};"
        : "+f"(d[0]), "+f"(d[1]), "+f"(d[2]), "+f"(d[3])
        : "r"(a[0]), "r"(a[1]), "r"(a[2]), "r"(a[3]), "r"(b[0]), "r"(b[1]));
}
__device__ __forceinline__ void pack_hilo(float v0, float v1, uint32_t& hi, uint32_t& lo) {
    __nv_bfloat16 h0 = __float2bfloat16(v0), h1 = __float2bfloat16(v1);
    __nv_bfloat162 hh; hh.x = h0; hh.y = h1;
    hi = *(uint32_t*)&hh;
    __nv_bfloat162 gg;
    gg.x = __float2bfloat16(v0 - __bfloat162float(h0));
    gg.y = __float2bfloat16(v1 - __bfloat162float(h1));
    lo = *(uint32_t*)&gg;
}

template <int KSTEPS>
__device__ __forceinline__ void do_layer(char* sm, int offAh, int offAl,
                                         int offBh, int offBl,
                                         int wrow0, int lane, float d[16][4]) {
    uint32_t aHi = smem_u32(sm + offAh) + (uint32_t)(wrow0 + (lane & 15)) * PITCH
                   + ((lane >> 4) << 4);
    uint32_t aLo = smem_u32(sm + offAl) + (uint32_t)(wrow0 + (lane & 15)) * PITCH
                   + ((lane >> 4) << 4);
    uint32_t bprow = (uint32_t)((lane & 7) + ((lane >> 3) & 1) * 8) * PITCH
                     + (uint32_t)((lane >> 4) << 4);
    uint32_t bHi0 = smem_u32(sm + offBh) + bprow;
    uint32_t bLo0 = smem_u32(sm + offBl) + bprow;
#pragma unroll
    for (int ks = 0; ks < KSTEPS; ks++) {
        uint32_t ah[4], al[4];
        ldsm_x4(aHi + ks * 32, ah);
        ldsm_x4(aLo + ks * 32, al);
        uint32_t bh_b = bHi0 + (uint32_t)ks * 16 * PITCH;
        uint32_t bl_b = bLo0 + (uint32_t)ks * 16 * PITCH;
#pragma unroll
        for (int ntp = 0; ntp < 8; ntp++) {
            uint32_t bh[4], bl[4];
            ldsm_x4t(bh_b + ntp * 32, bh);
            ldsm_x4t(bl_b + ntp * 32, bl);
            mma16816(d[2*ntp],     ah, bh);
            mma16816(d[2*ntp],     ah, bl);
            mma16816(d[2*ntp],     al, bh);
            mma16816(d[2*ntp + 1], ah, bh + 2);
            mma16816(d[2*ntp + 1], ah, bl + 2);
            mma16816(d[2*ntp + 1], al, bh + 2);
        }
    }
}

extern __shared__ __align__(128) char mlps[];

__global__ __launch_bounds__(256, 1) void consumer_kernel(
    const float* __restrict__ x, const float* __restrict__ pos,
    const float* __restrict__ W1, const float* __restrict__ b1,
    const float* __restrict__ W2, const float* __restrict__ b2,
    float* __restrict__ out, float* __restrict__ poss) {
    char* sm = mlps;
    float* b1s = (float*)(sm + OFF_B1);
    float* b2s = (float*)(sm + OFF_B2);
    float* wmx = (float*)(sm + OFF_WMX);

    int tid = threadIdx.x, lane = tid & 31, warp = tid >> 5;
    int wrow0 = warp * 16;

    // stage weights hi/lo into [k][n] pitch-136 layout (once)
    for (int i = tid; i < 80 * 128; i += 256) {
        int kk = i >> 7, n = i & 127;
        float v = (kk < CIN) ? W1[kk * Hd + n] : 0.f;
        __nv_bfloat16 hv = __float2bfloat16(v);
        *(__nv_bfloat16*)(sm + OFF_W1H + kk * PITCH + n * 2) = hv;
        *(__nv_bfloat16*)(sm + OFF_W1L + kk * PITCH + n * 2) =
            __float2bfloat16(v - __bfloat162float(hv));
    }
    for (int i = tid; i < 128 * 128; i += 256) {
        int kk = i >> 7, n = i & 127;
        float v = W2[kk * Hd + n];
        __nv_bfloat16 hv = __float2bfloat16(v);
        *(__nv_bfloat16*)(sm + OFF_W2H + kk * PITCH + n * 2) = hv;
        *(__nv_bfloat16*)(sm + OFF_W2L + kk * PITCH + n * 2) =
            __float2bfloat16(v - __bfloat162float(hv));
    }
    if (tid < Hd) { b1s[tid] = b1[tid]; b2s[tid] = b2[tid]; }

    __shared__ int   s_w;
    __shared__ int   snbr[2][Kn];
    __shared__ int   scnt[2];
    __shared__ float sctr[2][3];

    while (true) {
        if (tid == 0) s_w = atomicAdd(&g_work, 1);
        __syncthreads();
        int wk = s_w;
        if (wk >= Bsz * Mc / 2) break;
        int b  = wk & (Bsz - 1);
        int pp = wk >> 4;
        int bc = (b << 10) + (pp << 1);

        if (tid == 0) {
            int need = (pp << 1) + 2;
            while (ld_acq(&g_prog[b]) < need) __nanosleep(128);
        }
        __syncthreads();

        // ---- inline radius query (warps 0/1, one center each) ----------
        if (warp < 2) {
            int cm = bc + warp;
            int ci = g_idx[cm];
            const float* p2 = pos + b * Npt * 3;
            float sx = p2[ci*3+0], sy = p2[ci*3+1], sz = p2[ci*3+2];
            if (lane == 0) {
                poss[cm*3+0] = sx; poss[cm*3+1] = sy; poss[cm*3+2] = sz;
                sctr[warp][0] = sx; sctr[warp][1] = sy; sctr[warp][2] = sz;
            }
            float sn = __fadd_rn(__fadd_rn(__fmul_rn(sx,sx), __fmul_rn(sy,sy)),
                                 __fmul_rn(sz,sz));
            const float R2 = 0.2f * 0.2f;
            int cnt = 0;
            for (int base = 0; base < Npt; base += 32) {
                int   i = base + lane;
                float xx = p2[i*3+0], yy = p2[i*3+1], zz = p2[i*3+2];
                float pn = __fadd_rn(__fadd_rn(__fmul_rn(xx,xx), __fmul_rn(yy,yy)),
                                     __fmul_rn(zz,zz));
                float dot = __fadd_rn(__fadd_rn(__fmul_rn(sx,xx), __fmul_rn(sy,yy)),
                                      __fmul_rn(sz,zz));
                float d2 = __fsub_rn(__fadd_rn(sn, pn), __fmul_rn(2.0f, dot));
                bool  in = (d2 <= R2);
                unsigned ball = __ballot_sync(0xffffffffu, in);
                if (in) {
                    int ppos = cnt + __popc(ball & ((1u << lane) - 1u));
                    if (ppos < Kn) snbr[warp][ppos] = i;
                }
                cnt += __popc(ball);
                if (cnt >= Kn) break;
            }
            if (cnt > Kn) cnt = Kn;
            for (int k2 = cnt + lane; k2 < Kn; k2 += 32) snbr[warp][k2] = 0;
            if (lane == 0) scnt[warp] = cnt;
        }
        __syncthreads();

        // ---- gather (rows warp-local) -----------------------------------
        {
            int r = tid >> 1, h = tid & 1;
            int c = r >> 6;
            int k = r & 63;
            int nb = snbr[c][k];
            const float* xr = x + ((size_t)b * Npt + nb) * Cft + h * 32;
            char* fh = sm + OFF_FH + r * PITCH + h * 64;
            char* fl = sm + OFF_FL + r * PITCH + h * 64;
#pragma unroll
            for (int j = 0; j < 8; j++) {
                float4 v = *(const float4*)(xr + j * 4);
                uint32_t h0, l0, h1v, l1v;
                pack_hilo(v.x, v.y, h0, l0);
                pack_hilo(v.z, v.w, h1v, l1v);
                *(uint32_t*)(fh + j * 8)     = h0;
                *(uint32_t*)(fh + j * 8 + 4) = h1v;
                *(uint32_t*)(fl + j * 8)     = l0;
                *(uint32_t*)(fl + j * 8 + 4) = l1v;
            }
            if (h == 0) {
                const float* pb = pos + b * Npt * 3;
                float pd0 = pb[nb*3+0] - sctr[c][0];
                float pd1 = pb[nb*3+1] - sctr[c][1];
                float pd2 = pb[nb*3+2] - sctr[c][2];
                char* fh2 = sm + OFF_FH + r * PITCH + 128;
                char* fl2 = sm + OFF_FL + r * PITCH + 128;
                uint32_t h0, l0, h1v, l1v;
                pack_hilo(pd0, pd1, h0, l0);
                pack_hilo(pd2, 0.f, h1v, l1v);
                *(uint32_t*)(fh2)     = h0;  *(uint32_t*)(fh2 + 4) = h1v;
                *(uint32_t*)(fl2)     = l0;  *(uint32_t*)(fl2 + 4) = l1v;
#pragma unroll
                for (int j = 2; j < 8; j++) {
                    *(uint32_t*)(fh2 + j * 4) = 0u;
                    *(uint32_t*)(fl2 + j * 4) = 0u;
                }
            }
        }
        __syncwarp();

        // ---- layer 1 (K=80) ---------------------------------------------
        float d[16][4];
#pragma unroll
        for (int nt = 0; nt < 16; nt++)
#pragma unroll
            for (int q = 0; q < 4; q++) d[nt][q] = 0.f;
        do_layer<5>(sm, OFF_FH, OFF_FL, OFF_W1H, OFF_W1L, wrow0, lane, d);

        // ---- epilogue 1 ---------------------------------------------------
        {
            int r0 = wrow0 + (lane >> 2);
#pragma unroll
            for (int nt = 0; nt < 16; nt++) {
                int c0 = nt * 8 + (lane & 3) * 2;
                float v00 = fmaxf(d[nt][0] + b1s[c0],     0.f);
                float v01 = fmaxf(d[nt][1] + b1s[c0 + 1], 0.f);
                float v10 = fmaxf(d[nt][2] + b1s[c0],     0.f);
                float v11 = fmaxf(d[nt][3] + b1s[c0 + 1], 0.f);
                uint32_t h0, l0, h1v, l1v;
                pack_hilo(v00, v01, h0, l0);
                pack_hilo(v10, v11, h1v, l1v);
                *(uint32_t*)(sm + OFF_FH + r0 * PITCH + c0 * 2)       = h0;
                *(uint32_t*)(sm + OFF_FL + r0 * PITCH + c0 * 2)       = l0;
                *(uint32_t*)(sm + OFF_FH + (r0 + 8) * PITCH + c0 * 2) = h1v;
                *(uint32_t*)(sm + OFF_FL + (r0 + 8) * PITCH + c0 * 2) = l1v;
            }
        }
        __syncwarp();

        // ---- layer 2 (K=128) ----------------------------------------------
#pragma unroll
        for (int nt = 0; nt < 16; nt++)
#pragma unroll
            for (int q = 0; q < 4; q++) d[nt][q] = 0.f;
        do_layer<8>(sm, OFF_FH, OFF_FL, OFF_W2H, OFF_W2L, wrow0, lane, d);

        // ---- epilogue 2 ----------------------------------------------------
        {
            int cnt_w = scnt[warp >> 2];
            int k0 = (wrow0 & 63) + (lane >> 2);
            bool va = k0 < cnt_w, vb = (k0 + 8) < cnt_w;
#pragma unroll
            for (int nt = 0; nt < 16; nt++) {
                int c0 = nt * 8 + (lane & 3) * 2;
                float m0 = fmaxf(va ? fmaxf(d[nt][0] + b2s[c0], 0.f) : 0.f,
                                 vb ? fmaxf(d[nt][2] + b2s[c0], 0.f) : 0.f);
                float m1 = fmaxf(va ? fmaxf(d[nt][1] + b2s[c0 + 1], 0.f) : 0.f,
                                 vb ? fmaxf(d[nt][3] + b2s[c0 + 1], 0.f) : 0.f);
#pragma unroll
                for (int o = 4; o <= 16; o <<= 1) {
                    m0 = fmaxf(m0, __shfl_xor_sync(0xffffffffu, m0, o));
                    m1 = fmaxf(m1, __shfl_xor_sync(0xffffffffu, m1, o));
                }
                if (lane < 4) {
                    wmx[warp * 128 + c0]     = m0;
                    wmx[warp * 128 + c0 + 1] = m1;
                }
            }
        }
        __syncthreads();
        {
            int col = tid & 127, ctr = tid >> 7;
            float mv = fmaxf(
                fmaxf(wmx[(ctr * 4 + 0) * 128 + col], wmx[(ctr * 4 + 1) * 128 + col]),
                fmaxf(wmx[(ctr * 4 + 2) * 128 + col], wmx[(ctr * 4 + 3) * 128 + col]));
            int cmo = bc + ctr;
            out[(size_t)cmo * Hd + col] = (scnt[ctr] > 0) ? mv : 0.f;
        }
    }
}

__global__ void init_kernel() {
    if (threadIdx.x < Bsz) g_prog[threadIdx.x] = 0;
    if (threadIdx.x == 0) g_work = 0;
}

// ============================ launch (forked-stream graph) =================
extern "C" void kernel_launch(void* const* d_in, const int* in_sizes, int n_in,
                              void* d_out, int out_size) {
    const float* x   = (const float*)d_in[0];
    const float* pos = (const float*)d_in[1];
    const float* W1  = (const float*)d_in[2];
    const float* b1  = (const float*)d_in[3];
    const float* W2  = (const float*)d_in[4];
    const float* b2  = (const float*)d_in[5];
    float* out = (float*)d_out;

    float* poss;
    if (out_size >= Bsz * Mc * (Hd + 3)) {
        poss = out + (size_t)Bsz * Mc * Hd;
    } else {
        void* tmp = nullptr;
        cudaGetSymbolAddress(&tmp, g_poss_dump);
        poss = (float*)tmp;
    }

    static cudaStream_t s2 = nullptr;
    static cudaEvent_t evFork = nullptr, evJoin = nullptr;
    if (s2 == nullptr) {
        cudaStreamCreateWithFlags(&s2, cudaStreamNonBlocking);
        cudaEventCreateWithFlags(&evFork, cudaEventDisableTiming);
        cudaEventCreateWithFlags(&evJoin, cudaEventDisableTiming);
    }
    cudaFuncSetAttribute(consumer_kernel, cudaFuncAttributeMaxDynamicSharedMemorySize,
                         MLP_SMEM);
    cudaFuncSetAttribute(fps_kernel, cudaFuncAttributeMaxDynamicSharedMemorySize,
                         3 * Npt * 4);

    // init -> fork: {FPS on s2} || {consumer on default} -> join
    init_kernel<<<1, 32>>>();
    cudaEventRecord(evFork, 0);
    cudaStreamWaitEvent(s2, evFork, 0);
    fps_kernel<<<Bsz, FPS_T, 3 * Npt * 4, s2>>>(pos);
    consumer_kernel<<<136, 256, MLP_SMEM>>>(x, pos, W1, b1, W2, b2, out, poss);
    cudaEventRecord(evJoin, s2);
    cudaStreamWaitEvent(0, evJoin, 0);
}

// round 12
// speedup vs baseline: 2.1187x; 2.1187x over previous
#include <cuda_runtime.h>
#include <cuda_bf16.h>
#include <float.h>
#include <stdint.h>

#define Bsz 16
#define Npt 4096
#define Cft 64
#define Mc  1024
#define Kn  64
#define Hd  128
#define CIN 67

__device__ int   g_idx[Bsz*Mc];
__device__ int   g_nbr[Bsz*Mc*Kn];
__device__ int   g_cnt[Bsz*Mc];
__device__ float g_ctr[Bsz*Mc*3];
__device__ float g_poss_dump[Bsz*Mc*3];

// ============================ 1) FPS (R9/R5 exact, 402us) =================
#define FPS_T 1024
#define FPPT 4
extern __shared__ float fps_sm[];

__global__ __launch_bounds__(FPS_T) void fps_kernel(const float* __restrict__ pos) {
    float* spx = fps_sm;
    float* spy = spx + Npt;
    float* spz = spy + Npt;
    __shared__ unsigned swv[2][32];
    __shared__ unsigned swc[2][32];

    int b = blockIdx.x;
    const float* p = pos + b * Npt * 3;
    int t = threadIdx.x, lane = t & 31, w = t >> 5;

    float px[FPPT], py[FPPT], pz[FPPT], dd[FPPT];
#pragma unroll
    for (int j = 0; j < FPPT; j++) {
        int i = t + j * FPS_T;
        float xx = p[i*3+0], yy = p[i*3+1], zz = p[i*3+2];
        px[j] = xx; py[j] = yy; pz[j] = zz;
        spx[i] = xx; spy[i] = yy; spz[i] = zz;
        dd[j] = FLT_MAX;
    }
    if (t == 0) g_idx[b * Mc] = 0;
    __syncthreads();

    int last = 0, par = 0;
    for (int s = 1; s < Mc; s++) {
        float lx = spx[last], ly = spy[last], lz = spz[last];
        unsigned vmx = 0u;
#pragma unroll
        for (int j = 0; j < FPPT; j++) {
            float dx = __fsub_rn(px[j], lx);
            float dy = __fsub_rn(py[j], ly);
            float dz = __fsub_rn(pz[j], lz);
            float d  = __fadd_rn(__fadd_rn(__fmul_rn(dx,dx), __fmul_rn(dy,dy)),
                                 __fmul_rn(dz,dz));
            float v = fminf(dd[j], d);
            dd[j] = v;
            unsigned vu = __float_as_uint(v);
            vmx = vmx > vu ? vmx : vu;
        }
        unsigned cand = 0x7fffffffu;
#pragma unroll
        for (int j = FPPT - 1; j >= 0; j--)
            if (__float_as_uint(dd[j]) == vmx) cand = (unsigned)(t + j * FPS_T);
        unsigned wmax = __reduce_max_sync(0xffffffffu, vmx);
        unsigned csel = (vmx == wmax) ? cand : 0x7fffffffu;
        unsigned wcnd = __reduce_min_sync(0xffffffffu, csel);
        if (lane == 0) { swv[par][w] = wmax; swc[par][w] = wcnd; }
        __syncthreads();
        unsigned vv = swv[par][lane], cc = swc[par][lane];
        unsigned vm  = __reduce_max_sync(0xffffffffu, vv);
        unsigned cmn = __reduce_min_sync(0xffffffffu, (vv == vm) ? cc : 0x7fffffffu);
        last = (int)cmn;
        par ^= 1;
        if (t == 0) g_idx[b * Mc + s] = last;
    }
}

// ============================ 2) radius query (unchanged) =================
#define QWARPS 8
__global__ __launch_bounds__(QWARPS * 32) void query_kernel(
    const float* __restrict__ pos, float* __restrict__ poss_out) {
    int cm   = blockIdx.x * QWARPS + (threadIdx.x >> 5);
    int lane = threadIdx.x & 31;
    int b    = cm >> 10;
    const float* p = pos + b * Npt * 3;

    int   ci = g_idx[cm];
    float sx = p[ci*3+0], sy = p[ci*3+1], sz = p[ci*3+2];
    if (lane == 0) {
        poss_out[cm*3+0] = sx; poss_out[cm*3+1] = sy; poss_out[cm*3+2] = sz;
        g_ctr[cm*3+0] = sx; g_ctr[cm*3+1] = sy; g_ctr[cm*3+2] = sz;
    }
    float sn = __fadd_rn(__fadd_rn(__fmul_rn(sx,sx), __fmul_rn(sy,sy)),
                         __fmul_rn(sz,sz));
    const float R2 = 0.2f * 0.2f;

    int cnt = 0;
    for (int base = 0; base < Npt; base += 32) {
        int   i = base + lane;
        float xx = p[i*3+0], yy = p[i*3+1], zz = p[i*3+2];
        float pn = __fadd_rn(__fadd_rn(__fmul_rn(xx,xx), __fmul_rn(yy,yy)),
                             __fmul_rn(zz,zz));
        float dot = __fadd_rn(__fadd_rn(__fmul_rn(sx,xx), __fmul_rn(sy,yy)),
                              __fmul_rn(sz,zz));
        float d2 = __fsub_rn(__fadd_rn(sn, pn), __fmul_rn(2.0f, dot));
        bool  in = (d2 <= R2);
        unsigned ball = __ballot_sync(0xffffffffu, in);
        if (in) {
            int ppos = cnt + __popc(ball & ((1u << lane) - 1u));
            if (ppos < Kn) g_nbr[cm * Kn + ppos] = i;
        }
        cnt += __popc(ball);
        if (cnt >= Kn) break;
    }
    if (cnt > Kn) cnt = Kn;
    for (int k = cnt + lane; k < Kn; k += 32) g_nbr[cm * Kn + k] = 0;
    if (lane == 0) g_cnt[cm] = cnt;
}

// ============================ 3) MLP: mma.sync bf16x3, 16 warps ===========
// 512 thr = 16 warps (4/SMSP). Warp w: rows (w&7)*16, col-half (w>>3)*64.
// Same MMA math/order per output element as R9 -> bit-identical results.

#define PITCH 272
#define OFF_W1H 0
#define OFF_W1L 21760
#define OFF_W2H 43520
#define OFF_W2L 78336
#define OFF_FH  113152
#define OFF_FL  147968
#define OFF_B1  182784
#define OFF_B2  183296
#define OFF_WMX 183808
#define MLP_SMEM 187904

__device__ __forceinline__ uint32_t smem_u32(const void* p) {
    uint32_t a;
    asm("{ .reg .u64 t; cvta.to.shared.u64 t, %1; cvt.u32.u64 %0, t; }"
        : "=r"(a) : "l"(p));
    return a;
}
__device__ __forceinline__ void ldsm_x4(uint32_t addr, uint32_t* r) {
    asm volatile("ldmatrix.sync.aligned.m8n8.x4.shared.b16 {%0,%1,%2,%3}, [%4];"
        : "=r"(r[0]), "=r"(r[1]), "=r"(r[2]), "=r"(r[3]) : "r"(addr));
}
__device__ __forceinline__ void ldsm_x4t(uint32_t addr, uint32_t* r) {
    asm volatile("ldmatrix.sync.aligned.m8n8.x4.trans.shared.b16 {%0,%1,%2,%3}, [%4];"
        : "=r"(r[0]), "=r"(r[1]), "=r"(r[2]), "=r"(r[3]) : "r"(addr));
}
__device__ __forceinline__ void mma16816(float* d, const uint32_t* a, const uint32_t* b) {
    asm volatile("mma.sync.aligned.m16n8k16.row.col.f32.bf16.bf16.f32 "
        "{%0,%1,%2,%3}, {%4,%5,%6,%7}, {%8,%9}, {%0,%1,%2,%3};"
        : "+f"(d[0]), "+f"(d[1]), "+f"(d[2]), "+f"(d[3])
        : "r"(a[0]), "r"(a[1]), "r"(a[2]), "r"(a[3]), "r"(b[0]), "r"(b[1]));
}
__device__ __forceinline__ void pack_hilo(float v0, float v1, uint32_t& hi, uint32_t& lo) {
    __nv_bfloat16 h0 = __float2bfloat16(v0), h1 = __float2bfloat16(v1);
    __nv_bfloat162 hh; hh.x = h0; hh.y = h1;
    hi = *(uint32_t*)&hh;
    __nv_bfloat162 gg;
    gg.x = __float2bfloat16(v0 - __bfloat162float(h0));
    gg.y = __float2bfloat16(v1 - __bfloat162float(h1));
    lo = *(uint32_t*)&gg;
}

// Warp computes 16 rows x 64 cols (8 n-tiles) of D.
template <int KSTEPS>
__device__ __forceinline__ void do_layer(char* sm, int offAh, int offAl,
                                         int offBh, int offBl,
                                         int wrow0, int colbase,
                                         int lane, float d[8][4]) {
    uint32_t aHi = smem_u32(sm + offAh) + (uint32_t)(wrow0 + (lane & 15)) * PITCH
                   + ((lane >> 4) << 4);
    uint32_t aLo = smem_u32(sm + offAl) + (uint32_t)(wrow0 + (lane & 15)) * PITCH
                   + ((lane >> 4) << 4);
    uint32_t bprow = (uint32_t)((lane & 7) + ((lane >> 3) & 1) * 8) * PITCH
                     + (uint32_t)((lane >> 4) << 4) + (uint32_t)colbase * 2;
    uint32_t bHi0 = smem_u32(sm + offBh) + bprow;
    uint32_t bLo0 = smem_u32(sm + offBl) + bprow;
#pragma unroll
    for (int ks = 0; ks < KSTEPS; ks++) {
        uint32_t ah[4], al[4];
        ldsm_x4(aHi + ks * 32, ah);
        ldsm_x4(aLo + ks * 32, al);
        uint32_t bh_b = bHi0 + (uint32_t)ks * 16 * PITCH;
        uint32_t bl_b = bLo0 + (uint32_t)ks * 16 * PITCH;
#pragma unroll
        for (int ntp = 0; ntp < 4; ntp++) {
            uint32_t bh[4], bl[4];
            ldsm_x4t(bh_b + ntp * 32, bh);
            ldsm_x4t(bl_b + ntp * 32, bl);
            // interleaved: same-accumulator MMAs are >=2 apart
            mma16816(d[2*ntp],     ah, bh);
            mma16816(d[2*ntp + 1], ah, bh + 2);
            mma16816(d[2*ntp],     ah, bl);
            mma16816(d[2*ntp + 1], ah, bl + 2);
            mma16816(d[2*ntp],     al, bh);
            mma16816(d[2*ntp + 1], al, bh + 2);
        }
    }
}

extern __shared__ __align__(128) char mlps[];

__global__ __launch_bounds__(512, 1) void mlp_kernel(
    const float* __restrict__ x, const float* __restrict__ pos,
    const float* __restrict__ W1, const float* __restrict__ b1,
    const float* __restrict__ W2, const float* __restrict__ b2,
    float* __restrict__ out) {
    char* sm = mlps;
    float* b1s = (float*)(sm + OFF_B1);
    float* b2s = (float*)(sm + OFF_B2);
    float* wmx = (float*)(sm + OFF_WMX);   // [16][64]

    int tid = threadIdx.x, lane = tid & 31, warp = tid >> 5;
    int rw      = warp & 7;          // row-warp 0..7
    int half    = warp >> 3;         // col half 0/1
    int wrow0   = rw * 16;
    int colbase = half * 64;

    // ---- stage weights hi/lo into [k][n] pitch-136 layout (once) --------
    for (int i = tid; i < 80 * 128; i += 512) {
        int kk = i >> 7, n = i & 127;
        float v = (kk < CIN) ? W1[kk * Hd + n] : 0.f;
        __nv_bfloat16 hv = __float2bfloat16(v);
        *(__nv_bfloat16*)(sm + OFF_W1H + kk * PITCH + n * 2) = hv;
        *(__nv_bfloat16*)(sm + OFF_W1L + kk * PITCH + n * 2) =
            __float2bfloat16(v - __bfloat162float(hv));
    }
    for (int i = tid; i < 128 * 128; i += 512) {
        int kk = i >> 7, n = i & 127;
        float v = W2[kk * Hd + n];
        __nv_bfloat16 hv = __float2bfloat16(v);
        *(__nv_bfloat16*)(sm + OFF_W2H + kk * PITCH + n * 2) = hv;
        *(__nv_bfloat16*)(sm + OFF_W2L + kk * PITCH + n * 2) =
            __float2bfloat16(v - __bfloat162float(hv));
    }
    if (tid < Hd) { b1s[tid] = b1[tid]; b2s[tid] = b2[tid]; }

    for (int bc = blockIdx.x * 2; bc < Bsz * Mc; bc += gridDim.x * 2) {
        int b = bc >> 10;
        __syncthreads();  // weights ready (1st iter) / buffers reusable

        // ---- gather feat rows (4 threads/row, 16 cols each) -------------
        {
            int r = tid >> 2, h = tid & 3;
            int cm = bc + (r >> 6);
            int k  = r & 63;
            int nb = __ldg(g_nbr + cm * Kn + k);
            const float* xr = x + ((size_t)b * Npt + nb) * Cft + h * 16;
            char* fh = sm + OFF_FH + r * PITCH + h * 32;
            char* fl = sm + OFF_FL + r * PITCH + h * 32;
#pragma unroll
            for (int j = 0; j < 4; j++) {
                float4 v = *(const float4*)(xr + j * 4);
                uint32_t h0, l0, h1v, l1v;
                pack_hilo(v.x, v.y, h0, l0);
                pack_hilo(v.z, v.w, h1v, l1v);
                *(uint32_t*)(fh + j * 8)     = h0;
                *(uint32_t*)(fh + j * 8 + 4) = h1v;
                *(uint32_t*)(fl + j * 8)     = l0;
                *(uint32_t*)(fl + j * 8 + 4) = l1v;
            }
            if (h == 0) {   // cols 64..79: pos diffs + zero pad
                const float* pb = pos + b * Npt * 3;
                float pd0 = pb[nb*3+0] - g_ctr[cm*3+0];
                float pd1 = pb[nb*3+1] - g_ctr[cm*3+1];
                float pd2 = pb[nb*3+2] - g_ctr[cm*3+2];
                char* fh2 = sm + OFF_FH + r * PITCH + 128;
                char* fl2 = sm + OFF_FL + r * PITCH + 128;
                uint32_t h0, l0, h1v, l1v;
                pack_hilo(pd0, pd1, h0, l0);
                pack_hilo(pd2, 0.f, h1v, l1v);
                *(uint32_t*)(fh2)     = h0;  *(uint32_t*)(fh2 + 4) = h1v;
                *(uint32_t*)(fl2)     = l0;  *(uint32_t*)(fl2 + 4) = l1v;
#pragma unroll
                for (int j = 2; j < 8; j++) {
                    *(uint32_t*)(fh2 + j * 4) = 0u;
                    *(uint32_t*)(fl2 + j * 4) = 0u;
                }
            }
        }
        __syncthreads();

        // ---- layer 1 (K=80) ----------------------------------------------
        float d[8][4];
#pragma unroll
        for (int nt = 0; nt < 8; nt++)
#pragma unroll
            for (int q = 0; q < 4; q++) d[nt][q] = 0.f;
        do_layer<5>(sm, OFF_FH, OFF_FL, OFF_W1H, OFF_W1L, wrow0, colbase, lane, d);

        // ---- epilogue 1: relu(D+b1) -> h1 (own rows x own col half) ------
        {
            int r0 = wrow0 + (lane >> 2);
#pragma unroll
            for (int nt = 0; nt < 8; nt++) {
                int c0 = colbase + nt * 8 + (lane & 3) * 2;
                float v00 = fmaxf(d[nt][0] + b1s[c0],     0.f);
                float v01 = fmaxf(d[nt][1] + b1s[c0 + 1], 0.f);
                float v10 = fmaxf(d[nt][2] + b1s[c0],     0.f);
                float v11 = fmaxf(d[nt][3] + b1s[c0 + 1], 0.f);
                uint32_t h0, l0, h1v, l1v;
                pack_hilo(v00, v01, h0, l0);
                pack_hilo(v10, v11, h1v, l1v);
                *(uint32_t*)(sm + OFF_FH + r0 * PITCH + c0 * 2)       = h0;
                *(uint32_t*)(sm + OFF_FL + r0 * PITCH + c0 * 2)       = l0;
                *(uint32_t*)(sm + OFF_FH + (r0 + 8) * PITCH + c0 * 2) = h1v;
                *(uint32_t*)(sm + OFF_FL + (r0 + 8) * PITCH + c0 * 2) = l1v;
            }
        }
        __syncthreads();   // col halves cross warps now

        // ---- layer 2 (K=128) ----------------------------------------------
#pragma unroll
        for (int nt = 0; nt < 8; nt++)
#pragma unroll
            for (int q = 0; q < 4; q++) d[nt][q] = 0.f;
        do_layer<8>(sm, OFF_FH, OFF_FL, OFF_W2H, OFF_W2L, wrow0, colbase, lane, d);

        // ---- epilogue 2: bias+relu, mask, column max ----------------------
        {
            int cnt_w = __ldg(g_cnt + bc + (rw >> 2));
            int k0 = (wrow0 & 63) + (lane >> 2);
            bool va = k0 < cnt_w, vb = (k0 + 8) < cnt_w;
#pragma unroll
            for (int nt = 0; nt < 8; nt++) {
                int c0 = nt * 8 + (lane & 3) * 2;   // local col in half
                float m0 = fmaxf(va ? fmaxf(d[nt][0] + b2s[colbase + c0], 0.f) : 0.f,
                                 vb ? fmaxf(d[nt][2] + b2s[colbase + c0], 0.f) : 0.f);
                float m1 = fmaxf(va ? fmaxf(d[nt][1] + b2s[colbase + c0 + 1], 0.f) : 0.f,
                                 vb ? fmaxf(d[nt][3] + b2s[colbase + c0 + 1], 0.f) : 0.f);
#pragma unroll
                for (int o = 4; o <= 16; o <<= 1) {
                    m0 = fmaxf(m0, __shfl_xor_sync(0xffffffffu, m0, o));
                    m1 = fmaxf(m1, __shfl_xor_sync(0xffffffffu, m1, o));
                }
                if (lane < 4) {
                    wmx[warp * 64 + c0]     = m0;
                    wmx[warp * 64 + c0 + 1] = m1;
                }
            }
        }
        __syncthreads();
        if (tid < 256) {
            int col = tid & 127, ctr = tid >> 7;
            int hf = col >> 6, jj = col & 63;
            int base = (hf * 8 + ctr * 4) * 64 + jj;
            float mv = fmaxf(fmaxf(wmx[base], wmx[base + 64]),
                             fmaxf(wmx[base + 128], wmx[base + 192]));
            int cmo = bc + ctr;
            out[(size_t)cmo * Hd + col] = (__ldg(g_cnt + cmo) > 0) ? mv : 0.f;
        }
    }
}

// ============================ launch ======================================
extern "C" void kernel_launch(void* const* d_in, const int* in_sizes, int n_in,
                              void* d_out, int out_size) {
    const float* x   = (const float*)d_in[0];
    const float* pos = (const float*)d_in[1];
    const float* W1  = (const float*)d_in[2];
    const float* b1  = (const float*)d_in[3];
    const float* W2  = (const float*)d_in[4];
    const float* b2  = (const float*)d_in[5];
    float* out = (float*)d_out;

    float* poss;
    if (out_size >= Bsz * Mc * (Hd + 3)) {
        poss = out + (size_t)Bsz * Mc * Hd;
    } else {
        void* tmp = nullptr;
        cudaGetSymbolAddress(&tmp, g_poss_dump);
        poss = (float*)tmp;
    }

    cudaFuncSetAttribute(mlp_kernel, cudaFuncAttributeMaxDynamicSharedMemorySize,
                         MLP_SMEM);
    cudaFuncSetAttribute(fps_kernel, cudaFuncAttributeMaxDynamicSharedMemorySize,
                         3 * Npt * 4);

    fps_kernel<<<Bsz, FPS_T, 3 * Npt * 4>>>(pos);
    query_kernel<<<(Bsz * Mc) / QWARPS, QWARPS * 32>>>(pos, poss);
    mlp_kernel<<<152, 512, MLP_SMEM>>>(x, pos, W1, b1, W2, b2, out);
}

// round 14
// speedup vs baseline: 2.2867x; 1.0793x over previous
#include <cuda_runtime.h>
#include <cuda_bf16.h>
#include <float.h>
#include <stdint.h>

#define Bsz 16
#define Npt 4096
#define Cft 64
#define Mc  1024
#define Kn  64
#define Hd  128
#define CIN 67

__device__ int   g_idx[Bsz*Mc];
__device__ int   g_nbr[Bsz*Mc*Kn];
__device__ int   g_cnt[Bsz*Mc];
__device__ float g_ctr[Bsz*Mc*3];
__device__ float g_poss_dump[Bsz*Mc*3];

typedef unsigned long long ull;

// ---------------- f32x2 helpers (bit-exact per-lane IEEE fp32) ------------
__device__ __forceinline__ ull pack2(float a, float b) {
    ull d;
    asm("mov.b64 %0, {%1, %2};" : "=l"(d)
        : "r"(__float_as_uint(a)), "r"(__float_as_uint(b)));
    return d;
}
__device__ __forceinline__ ull add2(ull a, ull b) {
    ull d;
    asm("add.rn.f32x2 %0, %1, %2;" : "=l"(d) : "l"(a), "l"(b));
    return d;
}
__device__ __forceinline__ ull mul2(ull a, ull b) {
    ull d;
    asm("mul.rn.f32x2 %0, %1, %2;" : "=l"(d) : "l"(a), "l"(b));
    return d;
}
__device__ __forceinline__ void unpack2(ull v, float& lo, float& hi) {
    unsigned a, b;
    asm("mov.b64 {%0, %1}, %2;" : "=r"(a), "=r"(b) : "l"(v));
    lo = __uint_as_float(a);
    hi = __uint_as_float(b);
}

// ============================ 1) FPS (packed f32x2 distances) =============
// Same structure as the proven 401us kernel; distance math done 2 points per
// instruction via f32x2 (per-lane rounding identical to the scalar sequence,
// a+(-b) == a-b exactly) -> picks bit-identical, fewer issue slots per step.
#define FPS_T 1024
#define FPPT 4
extern __shared__ float fps_sm[];

__global__ __launch_bounds__(FPS_T) void fps_kernel(const float* __restrict__ pos) {
    float* spx = fps_sm;
    float* spy = spx + Npt;
    float* spz = spy + Npt;
    __shared__ unsigned swv[2][32];
    __shared__ unsigned swc[2][32];

    int b = blockIdx.x;
    const float* p = pos + b * Npt * 3;
    int t = threadIdx.x, lane = t & 31, w = t >> 5;

    float px[FPPT], py[FPPT], pz[FPPT], dd[FPPT];
#pragma unroll
    for (int j = 0; j < FPPT; j++) {
        int i = t + j * FPS_T;
        float xx = p[i*3+0], yy = p[i*3+1], zz = p[i*3+2];
        px[j] = xx; py[j] = yy; pz[j] = zz;
        spx[i] = xx; spy[i] = yy; spz[i] = zz;
        dd[j] = FLT_MAX;
    }
    // packed pairs: pair q = points (2q, 2q+1)
    ull px2[2], py2[2], pz2[2];
#pragma unroll
    for (int q = 0; q < 2; q++) {
        px2[q] = pack2(px[2*q], px[2*q+1]);
        py2[q] = pack2(py[2*q], py[2*q+1]);
        pz2[q] = pack2(pz[2*q], pz[2*q+1]);
    }
    if (t == 0) g_idx[b * Mc] = 0;
    __syncthreads();

    int last = 0, par = 0;
    for (int s = 1; s < Mc; s++) {
        float lx = spx[last], ly = spy[last], lz = spz[last];
        ull nlx2 = pack2(-lx, -lx);
        ull nly2 = pack2(-ly, -ly);
        ull nlz2 = pack2(-lz, -lz);
        unsigned vmx = 0u;
#pragma unroll
        for (int q = 0; q < 2; q++) {
            ull dx = add2(px2[q], nlx2);
            ull dy = add2(py2[q], nly2);
            ull dz = add2(pz2[q], nlz2);
            ull m  = add2(add2(mul2(dx, dx), mul2(dy, dy)), mul2(dz, dz));
            float d0, d1;
            unpack2(m, d0, d1);
            float v0 = fminf(dd[2*q],     d0);
            float v1 = fminf(dd[2*q + 1], d1);
            dd[2*q]     = v0;
            dd[2*q + 1] = v1;
            unsigned u0 = __float_as_uint(v0), u1 = __float_as_uint(v1);
            unsigned um = u0 > u1 ? u0 : u1;
            vmx = vmx > um ? vmx : um;
        }
        unsigned cand = 0x7fffffffu;
#pragma unroll
        for (int j = FPPT - 1; j >= 0; j--)
            if (__float_as_uint(dd[j]) == vmx) cand = (unsigned)(t + j * FPS_T);
        unsigned wmax = __reduce_max_sync(0xffffffffu, vmx);
        unsigned csel = (vmx == wmax) ? cand : 0x7fffffffu;
        unsigned wcnd = __reduce_min_sync(0xffffffffu, csel);
        if (lane == 0) { swv[par][w] = wmax; swc[par][w] = wcnd; }
        __syncthreads();
        unsigned vv = swv[par][lane], cc = swc[par][lane];
        unsigned vm  = __reduce_max_sync(0xffffffffu, vv);
        unsigned cmn = __reduce_min_sync(0xffffffffu, (vv == vm) ? cc : 0x7fffffffu);
        last = (int)cmn;
        par ^= 1;
        if (t == 0) g_idx[b * Mc + s] = last;
    }
}

// ============================ 2) radius query (R12 exact) =================
#define QWARPS 8
__global__ __launch_bounds__(QWARPS * 32) void query_kernel(
    const float* __restrict__ pos, float* __restrict__ poss_out) {
    int cm   = blockIdx.x * QWARPS + (threadIdx.x >> 5);
    int lane = threadIdx.x & 31;
    int b    = cm >> 10;
    const float* p = pos + b * Npt * 3;

    int   ci = g_idx[cm];
    float sx = p[ci*3+0], sy = p[ci*3+1], sz = p[ci*3+2];
    if (lane == 0) {
        poss_out[cm*3+0] = sx; poss_out[cm*3+1] = sy; poss_out[cm*3+2] = sz;
        g_ctr[cm*3+0] = sx; g_ctr[cm*3+1] = sy; g_ctr[cm*3+2] = sz;
    }
    float sn = __fadd_rn(__fadd_rn(__fmul_rn(sx,sx), __fmul_rn(sy,sy)),
                         __fmul_rn(sz,sz));
    const float R2 = 0.2f * 0.2f;

    int cnt = 0;
    for (int base = 0; base < Npt; base += 32) {
        int   i = base + lane;
        float xx = p[i*3+0], yy = p[i*3+1], zz = p[i*3+2];
        float pn = __fadd_rn(__fadd_rn(__fmul_rn(xx,xx), __fmul_rn(yy,yy)),
                             __fmul_rn(zz,zz));
        float dot = __fadd_rn(__fadd_rn(__fmul_rn(sx,xx), __fmul_rn(sy,yy)),
                              __fmul_rn(sz,zz));
        float d2 = __fsub_rn(__fadd_rn(sn, pn), __fmul_rn(2.0f, dot));
        bool  in = (d2 <= R2);
        unsigned ball = __ballot_sync(0xffffffffu, in);
        if (in) {
            int ppos = cnt + __popc(ball & ((1u << lane) - 1u));
            if (ppos < Kn) g_nbr[cm * Kn + ppos] = i;
        }
        cnt += __popc(ball);
        if (cnt >= Kn) break;
    }
    if (cnt > Kn) cnt = Kn;
    for (int k = cnt + lane; k < Kn; k += 32) g_nbr[cm * Kn + k] = 0;
    if (lane == 0) g_cnt[cm] = cnt;
}

// ============================ 3) MLP (R12 exact) ===========================
#define PITCH 272
#define OFF_W1H 0
#define OFF_W1L 21760
#define OFF_W2H 43520
#define OFF_W2L 78336
#define OFF_FH  113152
#define OFF_FL  147968
#define OFF_B1  182784
#define OFF_B2  183296
#define OFF_WMX 183808
#define MLP_SMEM 187904

__device__ __forceinline__ uint32_t smem_u32(const void* p) {
    uint32_t a;
    asm("{ .reg .u64 t; cvta.to.shared.u64 t, %1; cvt.u32.u64 %0, t; }"
        : "=r"(a) : "l"(p));
    return a;
}
__device__ __forceinline__ void ldsm_x4(uint32_t addr, uint32_t* r) {
    asm volatile("ldmatrix.sync.aligned.m8n8.x4.shared.b16 {%0,%1,%2,%3}, [%4];"
        : "=r"(r[0]), "=r"(r[1]), "=r"(r[2]), "=r"(r[3]) : "r"(addr));
}
__device__ __forceinline__ void ldsm_x4t(uint32_t addr, uint32_t* r) {
    asm volatile("ldmatrix.sync.aligned.m8n8.x4.trans.shared.b16 {%0,%1,%2,%3}, [%4];"
        : "=r"(r[0]), "=r"(r[1]), "=r"(r[2]), "=r"(r[3]) : "r"(addr));
}
__device__ __forceinline__ void mma16816(float* d, const uint32_t* a, const uint32_t* b) {
    asm volatile("mma.sync.aligned.m16n8k16.row.col.f32.bf16.bf16.f32 "
        "{%0,%1,%2,%3}, {%4,%5,%6,%7}, {%8,%9}, {%0,%1,%2,%3};"
        : "+f"(d[0]), "+f"(d[1]), "+f"(d[2]), "+f"(d[3])
        : "r"(a[0]), "r"(a[1]), "r"(a[2]), "r"(a[3]), "r"(b[0]), "r"(b[1]));
}
__device__ __forceinline__ void pack_hilo(float v0, float v1, uint32_t& hi, uint32_t& lo) {
    __nv_bfloat16 h0 = __float2bfloat16(v0), h1 = __float2bfloat16(v1);
    __nv_bfloat162 hh; hh.x = h0; hh.y = h1;
    hi = *(uint32_t*)&hh;
    __nv_bfloat162 gg;
    gg.x = __float2bfloat16(v0 - __bfloat162float(h0));
    gg.y = __float2bfloat16(v1 - __bfloat162float(h1));
    lo = *(uint32_t*)&gg;
}

template <int KSTEPS>
__device__ __forceinline__ void do_layer(char* sm, int offAh, int offAl,
                                         int offBh, int offBl,
                                         int wrow0, int colbase,
                                         int lane, float d[8][4]) {
    uint32_t aHi = smem_u32(sm + offAh) + (uint32_t)(wrow0 + (lane & 15)) * PITCH
                   + ((lane >> 4) << 4);
    uint32_t aLo = smem_u32(sm + offAl) + (uint32_t)(wrow0 + (lane & 15)) * PITCH
                   + ((lane >> 4) << 4);
    uint32_t bprow = (uint32_t)((lane & 7) + ((lane >> 3) & 1) * 8) * PITCH
                     + (uint32_t)((lane >> 4) << 4) + (uint32_t)colbase * 2;
    uint32_t bHi0 = smem_u32(sm + offBh) + bprow;
    uint32_t bLo0 = smem_u32(sm + offBl) + bprow;
#pragma unroll
    for (int ks = 0; ks < KSTEPS; ks++) {
        uint32_t ah[4], al[4];
        ldsm_x4(aHi + ks * 32, ah);
        ldsm_x4(aLo + ks * 32, al);
        uint32_t bh_b = bHi0 + (uint32_t)ks * 16 * PITCH;
        uint32_t bl_b = bLo0 + (uint32_t)ks * 16 * PITCH;
#pragma unroll
        for (int ntp = 0; ntp < 4; ntp++) {
            uint32_t bh[4], bl[4];
            ldsm_x4t(bh_b + ntp * 32, bh);
            ldsm_x4t(bl_b + ntp * 32, bl);
            mma16816(d[2*ntp],     ah, bh);
            mma16816(d[2*ntp + 1], ah, bh + 2);
            mma16816(d[2*ntp],     ah, bl);
            mma16816(d[2*ntp + 1], ah, bl + 2);
            mma16816(d[2*ntp],     al, bh);
            mma16816(d[2*ntp + 1], al, bh + 2);
        }
    }
}

extern __shared__ __align__(128) char mlps[];

__global__ __launch_bounds__(512, 1) void mlp_kernel(
    const float* __restrict__ x, const float* __restrict__ pos,
    const float* __restrict__ W1, const float* __restrict__ b1,
    const float* __restrict__ W2, const float* __restrict__ b2,
    float* __restrict__ out) {
    char* sm = mlps;
    float* b1s = (float*)(sm + OFF_B1);
    float* b2s = (float*)(sm + OFF_B2);
    float* wmx = (float*)(sm + OFF_WMX);

    int tid = threadIdx.x, lane = tid & 31, warp = tid >> 5;
    int rw      = warp & 7;
    int half    = warp >> 3;
    int wrow0   = rw * 16;
    int colbase = half * 64;

    for (int i = tid; i < 80 * 128; i += 512) {
        int kk = i >> 7, n = i & 127;
        float v = (kk < CIN) ? W1[kk * Hd + n] : 0.f;
        __nv_bfloat16 hv = __float2bfloat16(v);
        *(__nv_bfloat16*)(sm + OFF_W1H + kk * PITCH + n * 2) = hv;
        *(__nv_bfloat16*)(sm + OFF_W1L + kk * PITCH + n * 2) =
            __float2bfloat16(v - __bfloat162float(hv));
    }
    for (int i = tid; i < 128 * 128; i += 512) {
        int kk = i >> 7, n = i & 127;
        float v = W2[kk * Hd + n];
        __nv_bfloat16 hv = __float2bfloat16(v);
        *(__nv_bfloat16*)(sm + OFF_W2H + kk * PITCH + n * 2) = hv;
        *(__nv_bfloat16*)(sm + OFF_W2L + kk * PITCH + n * 2) =
            __float2bfloat16(v - __bfloat162float(hv));
    }
    if (tid < Hd) { b1s[tid] = b1[tid]; b2s[tid] = b2[tid]; }

    for (int bc = blockIdx.x * 2; bc < Bsz * Mc; bc += gridDim.x * 2) {
        int b = bc >> 10;
        __syncthreads();

        {
            int r = tid >> 2, h = tid & 3;
            int cm = bc + (r >> 6);
            int k  = r & 63;
            int nb = __ldg(g_nbr + cm * Kn + k);
            const float* xr = x + ((size_t)b * Npt + nb) * Cft + h * 16;
            char* fh = sm + OFF_FH + r * PITCH + h * 32;
            char* fl = sm + OFF_FL + r * PITCH + h * 32;
#pragma unroll
            for (int j = 0; j < 4; j++) {
                float4 v = *(const float4*)(xr + j * 4);
                uint32_t h0, l0, h1v, l1v;
                pack_hilo(v.x, v.y, h0, l0);
                pack_hilo(v.z, v.w, h1v, l1v);
                *(uint32_t*)(fh + j * 8)     = h0;
                *(uint32_t*)(fh + j * 8 + 4) = h1v;
                *(uint32_t*)(fl + j * 8)     = l0;
                *(uint32_t*)(fl + j * 8 + 4) = l1v;
            }
            if (h == 0) {
                const float* pb = pos + b * Npt * 3;
                float pd0 = pb[nb*3+0] - g_ctr[cm*3+0];
                float pd1 = pb[nb*3+1] - g_ctr[cm*3+1];
                float pd2 = pb[nb*3+2] - g_ctr[cm*3+2];
                char* fh2 = sm + OFF_FH + r * PITCH + 128;
                char* fl2 = sm + OFF_FL + r * PITCH + 128;
                uint32_t h0, l0, h1v, l1v;
                pack_hilo(pd0, pd1, h0, l0);
                pack_hilo(pd2, 0.f, h1v, l1v);
                *(uint32_t*)(fh2)     = h0;  *(uint32_t*)(fh2 + 4) = h1v;
                *(uint32_t*)(fl2)     = l0;  *(uint32_t*)(fl2 + 4) = l1v;
#pragma unroll
                for (int j = 2; j < 8; j++) {
                    *(uint32_t*)(fh2 + j * 4) = 0u;
                    *(uint32_t*)(fl2 + j * 4) = 0u;
                }
            }
        }
        __syncthreads();

        float d[8][4];
#pragma unroll
        for (int nt = 0; nt < 8; nt++)
#pragma unroll
            for (int q = 0; q < 4; q++) d[nt][q] = 0.f;
        do_layer<5>(sm, OFF_FH, OFF_FL, OFF_W1H, OFF_W1L, wrow0, colbase, lane, d);

        {
            int r0 = wrow0 + (lane >> 2);
#pragma unroll
            for (int nt = 0; nt < 8; nt++) {
                int c0 = colbase + nt * 8 + (lane & 3) * 2;
                float v00 = fmaxf(d[nt][0] + b1s[c0],     0.f);
                float v01 = fmaxf(d[nt][1] + b1s[c0 + 1], 0.f);
                float v10 = fmaxf(d[nt][2] + b1s[c0],     0.f);
                float v11 = fmaxf(d[nt][3] + b1s[c0 + 1], 0.f);
                uint32_t h0, l0, h1v, l1v;
                pack_hilo(v00, v01, h0, l0);
                pack_hilo(v10, v11, h1v, l1v);
                *(uint32_t*)(sm + OFF_FH + r0 * PITCH + c0 * 2)       = h0;
                *(uint32_t*)(sm + OFF_FL + r0 * PITCH + c0 * 2)       = l0;
                *(uint32_t*)(sm + OFF_FH + (r0 + 8) * PITCH + c0 * 2) = h1v;
                *(uint32_t*)(sm + OFF_FL + (r0 + 8) * PITCH + c0 * 2) = l1v;
            }
        }
        __syncthreads();

#pragma unroll
        for (int nt = 0; nt < 8; nt++)
#pragma unroll
            for (int q = 0; q < 4; q++) d[nt][q] = 0.f;
        do_layer<8>(sm, OFF_FH, OFF_FL, OFF_W2H, OFF_W2L, wrow0, colbase, lane, d);

        {
            int cnt_w = __ldg(g_cnt + bc + (rw >> 2));
            int k0 = (wrow0 & 63) + (lane >> 2);
            bool va = k0 < cnt_w, vb = (k0 + 8) < cnt_w;
#pragma unroll
            for (int nt = 0; nt < 8; nt++) {
                int c0 = nt * 8 + (lane & 3) * 2;
                float m0 = fmaxf(va ? fmaxf(d[nt][0] + b2s[colbase + c0], 0.f) : 0.f,
                                 vb ? fmaxf(d[nt][2] + b2s[colbase + c0], 0.f) : 0.f);
                float m1 = fmaxf(va ? fmaxf(d[nt][1] + b2s[colbase + c0 + 1], 0.f) : 0.f,
                                 vb ? fmaxf(d[nt][3] + b2s[colbase + c0 + 1], 0.f) : 0.f);
#pragma unroll
                for (int o = 4; o <= 16; o <<= 1) {
                    m0 = fmaxf(m0, __shfl_xor_sync(0xffffffffu, m0, o));
                    m1 = fmaxf(m1, __shfl_xor_sync(0xffffffffu, m1, o));
                }
                if (lane < 4) {
                    wmx[warp * 64 + c0]     = m0;
                    wmx[warp * 64 + c0 + 1] = m1;
                }
            }
        }
        __syncthreads();
        if (tid < 256) {
            int col = tid & 127, ctr = tid >> 7;
            int hf = col >> 6, jj = col & 63;
            int base = (hf * 8 + ctr * 4) * 64 + jj;
            float mv = fmaxf(fmaxf(wmx[base], wmx[base + 64]),
                             fmaxf(wmx[base + 128], wmx[base + 192]));
            int cmo = bc + ctr;
            out[(size_t)cmo * Hd + col] = (__ldg(g_cnt + cmo) > 0) ? mv : 0.f;
        }
    }
}

// ============================ launch ======================================
extern "C" void kernel_launch(void* const* d_in, const int* in_sizes, int n_in,
                              void* d_out, int out_size) {
    const float* x   = (const float*)d_in[0];
    const float* pos = (const float*)d_in[1];
    const float* W1  = (const float*)d_in[2];
    const float* b1  = (const float*)d_in[3];
    const float* W2  = (const float*)d_in[4];
    const float* b2  = (const float*)d_in[5];
    float* out = (float*)d_out;

    float* poss;
    if (out_size >= Bsz * Mc * (Hd + 3)) {
        poss = out + (size_t)Bsz * Mc * Hd;
    } else {
        void* tmp = nullptr;
        cudaGetSymbolAddress(&tmp, g_poss_dump);
        poss = (float*)tmp;
    }

    cudaFuncSetAttribute(mlp_kernel, cudaFuncAttributeMaxDynamicSharedMemorySize,
                         MLP_SMEM);
    cudaFuncSetAttribute(fps_kernel, cudaFuncAttributeMaxDynamicSharedMemorySize,
                         3 * Npt * 4);

    fps_kernel<<<Bsz, FPS_T, 3 * Npt * 4>>>(pos);
    query_kernel<<<(Bsz * Mc) / QWARPS, QWARPS * 32>>>(pos, poss);
    mlp_kernel<<<152, 512, MLP_SMEM>>>(x, pos, W1, b1, W2, b2, out);
}

// round 16
// speedup vs baseline: 2.3005x; 1.0060x over previous
#include <cuda_runtime.h>
#include <cuda_bf16.h>
#include <float.h>
#include <stdint.h>

#define Bsz 16
#define Npt 4096
#define Cft 64
#define Mc  1024
#define Kn  64
#define Hd  128
#define CIN 67

__device__ int   g_idx[Bsz*Mc];
__device__ int   g_nbr[Bsz*Mc*Kn];
__device__ int   g_cnt[Bsz*Mc];
__device__ float g_ctr[Bsz*Mc*3];
__device__ float g_poss_dump[Bsz*Mc*3];

typedef unsigned long long ull;

// ---------------- f32x2 helpers (bit-exact per-lane IEEE fp32) ------------
__device__ __forceinline__ ull pack2(float a, float b) {
    ull d;
    asm("mov.b64 %0, {%1, %2};" : "=l"(d)
        : "r"(__float_as_uint(a)), "r"(__float_as_uint(b)));
    return d;
}
__device__ __forceinline__ ull add2(ull a, ull b) {
    ull d;
    asm("add.rn.f32x2 %0, %1, %2;" : "=l"(d) : "l"(a), "l"(b));
    return d;
}
__device__ __forceinline__ ull mul2(ull a, ull b) {
    ull d;
    asm("mul.rn.f32x2 %0, %1, %2;" : "=l"(d) : "l"(a), "l"(b));
    return d;
}
__device__ __forceinline__ void unpack2(ull v, float& lo, float& hi) {
    unsigned a, b;
    asm("mov.b64 {%0, %1}, %2;" : "=r"(a), "=r"(b) : "l"(v));
    lo = __uint_as_float(a);
    hi = __uint_as_float(b);
}

// ============================ 1) FPS (R14 exact, 329us) ====================
#define FPS_T 1024
#define FPPT 4
extern __shared__ float fps_sm[];

__global__ __launch_bounds__(FPS_T) void fps_kernel(const float* __restrict__ pos) {
    float* spx = fps_sm;
    float* spy = spx + Npt;
    float* spz = spy + Npt;
    __shared__ unsigned swv[2][32];
    __shared__ unsigned swc[2][32];

    int b = blockIdx.x;
    const float* p = pos + b * Npt * 3;
    int t = threadIdx.x, lane = t & 31, w = t >> 5;

    float px[FPPT], py[FPPT], pz[FPPT], dd[FPPT];
#pragma unroll
    for (int j = 0; j < FPPT; j++) {
        int i = t + j * FPS_T;
        float xx = p[i*3+0], yy = p[i*3+1], zz = p[i*3+2];
        px[j] = xx; py[j] = yy; pz[j] = zz;
        spx[i] = xx; spy[i] = yy; spz[i] = zz;
        dd[j] = FLT_MAX;
    }
    ull px2[2], py2[2], pz2[2];
#pragma unroll
    for (int q = 0; q < 2; q++) {
        px2[q] = pack2(px[2*q], px[2*q+1]);
        py2[q] = pack2(py[2*q], py[2*q+1]);
        pz2[q] = pack2(pz[2*q], pz[2*q+1]);
    }
    if (t == 0) g_idx[b * Mc] = 0;
    __syncthreads();

    int last = 0, par = 0;
    for (int s = 1; s < Mc; s++) {
        float lx = spx[last], ly = spy[last], lz = spz[last];
        ull nlx2 = pack2(-lx, -lx);
        ull nly2 = pack2(-ly, -ly);
        ull nlz2 = pack2(-lz, -lz);
        unsigned vmx = 0u;
#pragma unroll
        for (int q = 0; q < 2; q++) {
            ull dx = add2(px2[q], nlx2);
            ull dy = add2(py2[q], nly2);
            ull dz = add2(pz2[q], nlz2);
            ull m  = add2(add2(mul2(dx, dx), mul2(dy, dy)), mul2(dz, dz));
            float d0, d1;
            unpack2(m, d0, d1);
            float v0 = fminf(dd[2*q],     d0);
            float v1 = fminf(dd[2*q + 1], d1);
            dd[2*q]     = v0;
            dd[2*q + 1] = v1;
            unsigned u0 = __float_as_uint(v0), u1 = __float_as_uint(v1);
            unsigned um = u0 > u1 ? u0 : u1;
            vmx = vmx > um ? vmx : um;
        }
        unsigned cand = 0x7fffffffu;
#pragma unroll
        for (int j = FPPT - 1; j >= 0; j--)
            if (__float_as_uint(dd[j]) == vmx) cand = (unsigned)(t + j * FPS_T);
        unsigned wmax = __reduce_max_sync(0xffffffffu, vmx);
        unsigned csel = (vmx == wmax) ? cand : 0x7fffffffu;
        unsigned wcnd = __reduce_min_sync(0xffffffffu, csel);
        if (lane == 0) { swv[par][w] = wmax; swc[par][w] = wcnd; }
        __syncthreads();
        unsigned vv = swv[par][lane], cc = swc[par][lane];
        unsigned vm  = __reduce_max_sync(0xffffffffu, vv);
        unsigned cmn = __reduce_min_sync(0xffffffffu, (vv == vm) ? cc : 0x7fffffffu);
        last = (int)cmn;
        par ^= 1;
        if (t == 0) g_idx[b * Mc + s] = last;
    }
}

// ============================ 2) radius query (R12 exact) =================
#define QWARPS 8
__global__ __launch_bounds__(QWARPS * 32) void query_kernel(
    const float* __restrict__ pos, float* __restrict__ poss_out) {
    int cm   = blockIdx.x * QWARPS + (threadIdx.x >> 5);
    int lane = threadIdx.x & 31;
    int b    = cm >> 10;
    const float* p = pos + b * Npt * 3;

    int   ci = g_idx[cm];
    float sx = p[ci*3+0], sy = p[ci*3+1], sz = p[ci*3+2];
    if (lane == 0) {
        poss_out[cm*3+0] = sx; poss_out[cm*3+1] = sy; poss_out[cm*3+2] = sz;
        g_ctr[cm*3+0] = sx; g_ctr[cm*3+1] = sy; g_ctr[cm*3+2] = sz;
    }
    float sn = __fadd_rn(__fadd_rn(__fmul_rn(sx,sx), __fmul_rn(sy,sy)),
                         __fmul_rn(sz,sz));
    const float R2 = 0.2f * 0.2f;

    int cnt = 0;
    for (int base = 0; base < Npt; base += 32) {
        int   i = base + lane;
        float xx = p[i*3+0], yy = p[i*3+1], zz = p[i*3+2];
        float pn = __fadd_rn(__fadd_rn(__fmul_rn(xx,xx), __fmul_rn(yy,yy)),
                             __fmul_rn(zz,zz));
        float dot = __fadd_rn(__fadd_rn(__fmul_rn(sx,xx), __fmul_rn(sy,yy)),
                              __fmul_rn(sz,zz));
        float d2 = __fsub_rn(__fadd_rn(sn, pn), __fmul_rn(2.0f, dot));
        bool  in = (d2 <= R2);
        unsigned ball = __ballot_sync(0xffffffffu, in);
        if (in) {
            int ppos = cnt + __popc(ball & ((1u << lane) - 1u));
            if (ppos < Kn) g_nbr[cm * Kn + ppos] = i;
        }
        cnt += __popc(ball);
        if (cnt >= Kn) break;
    }
    if (cnt > Kn) cnt = Kn;
    for (int k = cnt + lane; k < Kn; k += 32) g_nbr[cm * Kn + k] = 0;
    if (lane == 0) g_cnt[cm] = cnt;
}

// ============================ 3) MLP (3 barriers/iter + packed cvt) =======
#define PITCH 272
#define OFF_W1H 0
#define OFF_W1L 21760
#define OFF_W2H 43520
#define OFF_W2L 78336
#define OFF_FH  113152
#define OFF_FL  147968
#define OFF_B1  182784
#define OFF_B2  183296
#define OFF_WMX 183808
#define MLP_SMEM 187904

__device__ __forceinline__ uint32_t smem_u32(const void* p) {
    uint32_t a;
    asm("{ .reg .u64 t; cvta.to.shared.u64 t, %1; cvt.u32.u64 %0, t; }"
        : "=r"(a) : "l"(p));
    return a;
}
__device__ __forceinline__ void ldsm_x4(uint32_t addr, uint32_t* r) {
    asm volatile("ldmatrix.sync.aligned.m8n8.x4.shared.b16 {%0,%1,%2,%3}, [%4];"
        : "=r"(r[0]), "=r"(r[1]), "=r"(r[2]), "=r"(r[3]) : "r"(addr));
}
__device__ __forceinline__ void ldsm_x4t(uint32_t addr, uint32_t* r) {
    asm volatile("ldmatrix.sync.aligned.m8n8.x4.trans.shared.b16 {%0,%1,%2,%3}, [%4];"
        : "=r"(r[0]), "=r"(r[1]), "=r"(r[2]), "=r"(r[3]) : "r"(addr));
}
__device__ __forceinline__ void mma16816(float* d, const uint32_t* a, const uint32_t* b) {
    asm volatile("mma.sync.aligned.m16n8k16.row.col.f32.bf16.bf16.f32 "
        "{%0,%1,%2,%3}, {%4,%5,%6,%7}, {%8,%9}, {%0,%1,%2,%3};"
        : "+f"(d[0]), "+f"(d[1]), "+f"(d[2]), "+f"(d[3])
        : "r"(a[0]), "r"(a[1]), "r"(a[2]), "r"(a[3]), "r"(b[0]), "r"(b[1]));
}
// packed bf16 split via cvt.rn.bf16x2 (low half = v0; same RN rounding as
// scalar __float2bfloat16 -> bit-identical values, fewer instructions).
__device__ __forceinline__ void pack_hilo(float v0, float v1, uint32_t& hi, uint32_t& lo) {
    uint32_t h;
    asm("cvt.rn.bf16x2.f32 %0, %1, %2;" : "=r"(h) : "f"(v1), "f"(v0));
    __nv_bfloat162 hh = *reinterpret_cast<__nv_bfloat162*>(&h);
    float e0 = v0 - __bfloat162float(hh.x);
    float e1 = v1 - __bfloat162float(hh.y);
    uint32_t l;
    asm("cvt.rn.bf16x2.f32 %0, %1, %2;" : "=r"(l) : "f"(e1), "f"(e0));
    hi = h; lo = l;
}

template <int KSTEPS>
__device__ __forceinline__ void do_layer(char* sm, int offAh, int offAl,
                                         int offBh, int offBl,
                                         int wrow0, int colbase,
                                         int lane, float d[8][4]) {
    uint32_t aHi = smem_u32(sm + offAh) + (uint32_t)(wrow0 + (lane & 15)) * PITCH
                   + ((lane >> 4) << 4);
    uint32_t aLo = smem_u32(sm + offAl) + (uint32_t)(wrow0 + (lane & 15)) * PITCH
                   + ((lane >> 4) << 4);
    uint32_t bprow = (uint32_t)((lane & 7) + ((lane >> 3) & 1) * 8) * PITCH
                     + (uint32_t)((lane >> 4) << 4) + (uint32_t)colbase * 2;
    uint32_t bHi0 = smem_u32(sm + offBh) + bprow;
    uint32_t bLo0 = smem_u32(sm + offBl) + bprow;
#pragma unroll
    for (int ks = 0; ks < KSTEPS; ks++) {
        uint32_t ah[4], al[4];
        ldsm_x4(aHi + ks * 32, ah);
        ldsm_x4(aLo + ks * 32, al);
        uint32_t bh_b = bHi0 + (uint32_t)ks * 16 * PITCH;
        uint32_t bl_b = bLo0 + (uint32_t)ks * 16 * PITCH;
#pragma unroll
        for (int ntp = 0; ntp < 4; ntp++) {
            uint32_t bh[4], bl[4];
            ldsm_x4t(bh_b + ntp * 32, bh);
            ldsm_x4t(bl_b + ntp * 32, bl);
            mma16816(d[2*ntp],     ah, bh);
            mma16816(d[2*ntp + 1], ah, bh + 2);
            mma16816(d[2*ntp],     ah, bl);
            mma16816(d[2*ntp + 1], ah, bl + 2);
            mma16816(d[2*ntp],     al, bh);
            mma16816(d[2*ntp + 1], al, bh + 2);
        }
    }
}

extern __shared__ __align__(128) char mlps[];

__global__ __launch_bounds__(512, 1) void mlp_kernel(
    const float* __restrict__ x, const float* __restrict__ pos,
    const float* __restrict__ W1, const float* __restrict__ b1,
    const float* __restrict__ W2, const float* __restrict__ b2,
    float* __restrict__ out) {
    char* sm = mlps;
    float* b1s = (float*)(sm + OFF_B1);
    float* b2s = (float*)(sm + OFF_B2);
    float* wmx = (float*)(sm + OFF_WMX);

    int tid = threadIdx.x, lane = tid & 31, warp = tid >> 5;
    int rw      = warp & 7;
    int half    = warp >> 3;
    int wrow0   = rw * 16;
    int colbase = half * 64;

    for (int i = tid; i < 80 * 128; i += 512) {
        int kk = i >> 7, n = i & 127;
        float v = (kk < CIN) ? W1[kk * Hd + n] : 0.f;
        __nv_bfloat16 hv = __float2bfloat16(v);
        *(__nv_bfloat16*)(sm + OFF_W1H + kk * PITCH + n * 2) = hv;
        *(__nv_bfloat16*)(sm + OFF_W1L + kk * PITCH + n * 2) =
            __float2bfloat16(v - __bfloat162float(hv));
    }
    for (int i = tid; i < 128 * 128; i += 512) {
        int kk = i >> 7, n = i & 127;
        float v = W2[kk * Hd + n];
        __nv_bfloat16 hv = __float2bfloat16(v);
        *(__nv_bfloat16*)(sm + OFF_W2H + kk * PITCH + n * 2) = hv;
        *(__nv_bfloat16*)(sm + OFF_W2L + kk * PITCH + n * 2) =
            __float2bfloat16(v - __bfloat162float(hv));
    }
    if (tid < Hd) { b1s[tid] = b1[tid]; b2s[tid] = b2[tid]; }
    __syncthreads();   // weights ready (per-iter hazards covered below)

    for (int bc = blockIdx.x * 2; bc < Bsz * Mc; bc += gridDim.x * 2) {
        int b = bc >> 10;

        // gather feat rows. Safe without loop-top barrier: previous
        // iteration's feat/h1 reads completed before its epilogue-2 barrier.
        {
            int r = tid >> 2, h = tid & 3;
            int cm = bc + (r >> 6);
            int k  = r & 63;
            int nb = __ldg(g_nbr + cm * Kn + k);
            const float* xr = x + ((size_t)b * Npt + nb) * Cft + h * 16;
            char* fh = sm + OFF_FH + r * PITCH + h * 32;
            char* fl = sm + OFF_FL + r * PITCH + h * 32;
#pragma unroll
            for (int j = 0; j < 4; j++) {
                float4 v = *(const float4*)(xr + j * 4);
                uint32_t h0, l0, h1v, l1v;
                pack_hilo(v.x, v.y, h0, l0);
                pack_hilo(v.z, v.w, h1v, l1v);
                *(uint32_t*)(fh + j * 8)     = h0;
                *(uint32_t*)(fh + j * 8 + 4) = h1v;
                *(uint32_t*)(fl + j * 8)     = l0;
                *(uint32_t*)(fl + j * 8 + 4) = l1v;
            }
            if (h == 0) {
                const float* pb = pos + b * Npt * 3;
                float pd0 = pb[nb*3+0] - g_ctr[cm*3+0];
                float pd1 = pb[nb*3+1] - g_ctr[cm*3+1];
                float pd2 = pb[nb*3+2] - g_ctr[cm*3+2];
                char* fh2 = sm + OFF_FH + r * PITCH + 128;
                char* fl2 = sm + OFF_FL + r * PITCH + 128;
                uint32_t h0, l0, h1v, l1v;
                pack_hilo(pd0, pd1, h0, l0);
                pack_hilo(pd2, 0.f, h1v, l1v);
                *(uint32_t*)(fh2)     = h0;  *(uint32_t*)(fh2 + 4) = h1v;
                *(uint32_t*)(fl2)     = l0;  *(uint32_t*)(fl2 + 4) = l1v;
#pragma unroll
                for (int j = 2; j < 8; j++) {
                    *(uint32_t*)(fh2 + j * 4) = 0u;
                    *(uint32_t*)(fl2 + j * 4) = 0u;
                }
            }
        }
        __syncthreads();

        float d[8][4];
#pragma unroll
        for (int nt = 0; nt < 8; nt++)
#pragma unroll
            for (int q = 0; q < 4; q++) d[nt][q] = 0.f;
        do_layer<5>(sm, OFF_FH, OFF_FL, OFF_W1H, OFF_W1L, wrow0, colbase, lane, d);

        {
            int r0 = wrow0 + (lane >> 2);
#pragma unroll
            for (int nt = 0; nt < 8; nt++) {
                int c0 = colbase + nt * 8 + (lane & 3) * 2;
                float v00 = fmaxf(d[nt][0] + b1s[c0],     0.f);
                float v01 = fmaxf(d[nt][1] + b1s[c0 + 1], 0.f);
                float v10 = fmaxf(d[nt][2] + b1s[c0],     0.f);
                float v11 = fmaxf(d[nt][3] + b1s[c0 + 1], 0.f);
                uint32_t h0, l0, h1v, l1v;
                pack_hilo(v00, v01, h0, l0);
                pack_hilo(v10, v11, h1v, l1v);
                *(uint32_t*)(sm + OFF_FH + r0 * PITCH + c0 * 2)       = h0;
                *(uint32_t*)(sm + OFF_FL + r0 * PITCH + c0 * 2)       = l0;
                *(uint32_t*)(sm + OFF_FH + (r0 + 8) * PITCH + c0 * 2) = h1v;
                *(uint32_t*)(sm + OFF_FL + (r0 + 8) * PITCH + c0 * 2) = l1v;
            }
        }
        __syncthreads();

#pragma unroll
        for (int nt = 0; nt < 8; nt++)
#pragma unroll
            for (int q = 0; q < 4; q++) d[nt][q] = 0.f;
        do_layer<8>(sm, OFF_FH, OFF_FL, OFF_W2H, OFF_W2L, wrow0, colbase, lane, d);

        {
            int cnt_w = __ldg(g_cnt + bc + (rw >> 2));
            int k0 = (wrow0 & 63) + (lane >> 2);
            bool va = k0 < cnt_w, vb = (k0 + 8) < cnt_w;
#pragma unroll
            for (int nt = 0; nt < 8; nt++) {
                int c0 = nt * 8 + (lane & 3) * 2;
                float m0 = fmaxf(va ? fmaxf(d[nt][0] + b2s[colbase + c0], 0.f) : 0.f,
                                 vb ? fmaxf(d[nt][2] + b2s[colbase + c0], 0.f) : 0.f);
                float m1 = fmaxf(va ? fmaxf(d[nt][1] + b2s[colbase + c0 + 1], 0.f) : 0.f,
                                 vb ? fmaxf(d[nt][3] + b2s[colbase + c0 + 1], 0.f) : 0.f);
#pragma unroll
                for (int o = 4; o <= 16; o <<= 1) {
                    m0 = fmaxf(m0, __shfl_xor_sync(0xffffffffu, m0, o));
                    m1 = fmaxf(m1, __shfl_xor_sync(0xffffffffu, m1, o));
                }
                if (lane < 4) {
                    wmx[warp * 64 + c0]     = m0;
                    wmx[warp * 64 + c0 + 1] = m1;
                }
            }
        }
        __syncthreads();
        if (tid < 256) {
            int col = tid & 127, ctr = tid >> 7;
            int hf = col >> 6, jj = col & 63;
            int base = (hf * 8 + ctr * 4) * 64 + jj;
            float mv = fmaxf(fmaxf(wmx[base], wmx[base + 64]),
                             fmaxf(wmx[base + 128], wmx[base + 192]));
            int cmo = bc + ctr;
            out[(size_t)cmo * Hd + col] = (__ldg(g_cnt + cmo) > 0) ? mv : 0.f;
        }
    }
}

// ============================ launch ======================================
extern "C" void kernel_launch(void* const* d_in, const int* in_sizes, int n_in,
                              void* d_out, int out_size) {
    const float* x   = (const float*)d_in[0];
    const float* pos = (const float*)d_in[1];
    const float* W1  = (const float*)d_in[2];
    const float* b1  = (const float*)d_in[3];
    const float* W2  = (const float*)d_in[4];
    const float* b2  = (const float*)d_in[5];
    float* out = (float*)d_out;

    float* poss;
    if (out_size >= Bsz * Mc * (Hd + 3)) {
        poss = out + (size_t)Bsz * Mc * Hd;
    } else {
        void* tmp = nullptr;
        cudaGetSymbolAddress(&tmp, g_poss_dump);
        poss = (float*)tmp;
    }

    cudaFuncSetAttribute(mlp_kernel, cudaFuncAttributeMaxDynamicSharedMemorySize,
                         MLP_SMEM);
    cudaFuncSetAttribute(fps_kernel, cudaFuncAttributeMaxDynamicSharedMemorySize,
                         3 * Npt * 4);

    fps_kernel<<<Bsz, FPS_T, 3 * Npt * 4>>>(pos);
    query_kernel<<<(Bsz * Mc) / QWARPS, QWARPS * 32>>>(pos, poss);
    mlp_kernel<<<152, 512, MLP_SMEM>>>(x, pos, W1, b1, W2, b2, out);
}

// round 17
// speedup vs baseline: 2.3235x; 1.0100x over previous
#include <cuda_runtime.h>
#include <cuda_bf16.h>
#include <float.h>
#include <stdint.h>

#define Bsz 16
#define Npt 4096
#define Cft 64
#define Mc  1024
#define Kn  64
#define Hd  128
#define CIN 67

__device__ int   g_idx[Bsz*Mc];
__device__ int   g_nbr[Bsz*Mc*Kn];
__device__ int   g_cnt[Bsz*Mc];
__device__ float g_ctr[Bsz*Mc*3];
__device__ float g_poss_dump[Bsz*Mc*3];

typedef unsigned long long ull;

// ---------------- f32x2 helpers (bit-exact per-lane IEEE fp32) ------------
__device__ __forceinline__ ull pack2(float a, float b) {
    ull d;
    asm("mov.b64 %0, {%1, %2};" : "=l"(d)
        : "r"(__float_as_uint(a)), "r"(__float_as_uint(b)));
    return d;
}
__device__ __forceinline__ ull add2(ull a, ull b) {
    ull d;
    asm("add.rn.f32x2 %0, %1, %2;" : "=l"(d) : "l"(a), "l"(b));
    return d;
}
__device__ __forceinline__ ull mul2(ull a, ull b) {
    ull d;
    asm("mul.rn.f32x2 %0, %1, %2;" : "=l"(d) : "l"(a), "l"(b));
    return d;
}
__device__ __forceinline__ void unpack2(ull v, float& lo, float& hi) {
    unsigned a, b;
    asm("mov.b64 {%0, %1}, %2;" : "=r"(a), "=r"(b) : "l"(v));
    lo = __uint_as_float(a);
    hi = __uint_as_float(b);
}

// ============================ 1) FPS ======================================
// R16 arithmetic exactly; two issue-count cuts:
//  - broadcast point read as one LDS.128 from a float4-interleaved buffer
//  - max+first-index tracked via pairwise >= selection (lower index wins
//    ties at every level == jnp.argmax first-occurrence, same dd bits)
#define FPS_T 1024
#define FPPT 4
extern __shared__ float4 fps_sm4[];

__global__ __launch_bounds__(FPS_T) void fps_kernel(const float* __restrict__ pos) {
    float4* spp = fps_sm4;            // 4096 x float4 (x,y,z,0)
    __shared__ unsigned swv[2][32];
    __shared__ unsigned swc[2][32];

    int b = blockIdx.x;
    const float* p = pos + b * Npt * 3;
    int t = threadIdx.x, lane = t & 31, w = t >> 5;

    float px[FPPT], py[FPPT], pz[FPPT], dd[FPPT];
#pragma unroll
    for (int j = 0; j < FPPT; j++) {
        int i = t + j * FPS_T;
        float xx = p[i*3+0], yy = p[i*3+1], zz = p[i*3+2];
        px[j] = xx; py[j] = yy; pz[j] = zz;
        float4 v; v.x = xx; v.y = yy; v.z = zz; v.w = 0.f;
        spp[i] = v;
        dd[j] = FLT_MAX;
    }
    ull px2[2], py2[2], pz2[2];
#pragma unroll
    for (int q = 0; q < 2; q++) {
        px2[q] = pack2(px[2*q], px[2*q+1]);
        py2[q] = pack2(py[2*q], py[2*q+1]);
        pz2[q] = pack2(pz[2*q], pz[2*q+1]);
    }
    unsigned idx0 = (unsigned)t;
    unsigned idx1 = (unsigned)(t + FPS_T);
    unsigned idx2 = (unsigned)(t + 2 * FPS_T);
    unsigned idx3 = (unsigned)(t + 3 * FPS_T);
    if (t == 0) g_idx[b * Mc] = 0;
    __syncthreads();

    int last = 0, par = 0;
    for (int s = 1; s < Mc; s++) {
        float4 L = spp[last];          // one LDS.128 broadcast
        ull nlx2 = pack2(-L.x, -L.x);
        ull nly2 = pack2(-L.y, -L.y);
        ull nlz2 = pack2(-L.z, -L.z);

        unsigned u0, u1, u2, u3;
        {
            ull dx = add2(px2[0], nlx2);
            ull dy = add2(py2[0], nly2);
            ull dz = add2(pz2[0], nlz2);
            ull m  = add2(add2(mul2(dx, dx), mul2(dy, dy)), mul2(dz, dz));
            float d0, d1;
            unpack2(m, d0, d1);
            float v0 = fminf(dd[0], d0);
            float v1 = fminf(dd[1], d1);
            dd[0] = v0; dd[1] = v1;
            u0 = __float_as_uint(v0); u1 = __float_as_uint(v1);
        }
        {
            ull dx = add2(px2[1], nlx2);
            ull dy = add2(py2[1], nly2);
            ull dz = add2(pz2[1], nlz2);
            ull m  = add2(add2(mul2(dx, dx), mul2(dy, dy)), mul2(dz, dz));
            float d0, d1;
            unpack2(m, d0, d1);
            float v0 = fminf(dd[2], d0);
            float v1 = fminf(dd[3], d1);
            dd[2] = v0; dd[3] = v1;
            u2 = __float_as_uint(v0); u3 = __float_as_uint(v1);
        }
        // pairwise max with first-index tie-break (>= keeps lower index)
        bool     k01 = (u0 >= u1);
        unsigned m01 = k01 ? u0 : u1;
        unsigned i01 = k01 ? idx0 : idx1;
        bool     k23 = (u2 >= u3);
        unsigned m23 = k23 ? u2 : u3;
        unsigned i23 = k23 ? idx2 : idx3;
        bool     kf  = (m01 >= m23);
        unsigned vmx  = kf ? m01 : m23;
        unsigned cand = kf ? i01 : i23;

        unsigned wmax = __reduce_max_sync(0xffffffffu, vmx);
        unsigned csel = (vmx == wmax) ? cand : 0x7fffffffu;
        unsigned wcnd = __reduce_min_sync(0xffffffffu, csel);
        if (lane == 0) { swv[par][w] = wmax; swc[par][w] = wcnd; }
        __syncthreads();
        unsigned vv = swv[par][lane], cc = swc[par][lane];
        unsigned vm  = __reduce_max_sync(0xffffffffu, vv);
        unsigned cmn = __reduce_min_sync(0xffffffffu, (vv == vm) ? cc : 0x7fffffffu);
        last = (int)cmn;
        par ^= 1;
        if (t == 0) g_idx[b * Mc + s] = last;
    }
}

// ============================ 2) radius query (R16 exact) =================
#define QWARPS 8
__global__ __launch_bounds__(QWARPS * 32) void query_kernel(
    const float* __restrict__ pos, float* __restrict__ poss_out) {
    int cm   = blockIdx.x * QWARPS + (threadIdx.x >> 5);
    int lane = threadIdx.x & 31;
    int b    = cm >> 10;
    const float* p = pos + b * Npt * 3;

    int   ci = g_idx[cm];
    float sx = p[ci*3+0], sy = p[ci*3+1], sz = p[ci*3+2];
    if (lane == 0) {
        poss_out[cm*3+0] = sx; poss_out[cm*3+1] = sy; poss_out[cm*3+2] = sz;
        g_ctr[cm*3+0] = sx; g_ctr[cm*3+1] = sy; g_ctr[cm*3+2] = sz;
    }
    float sn = __fadd_rn(__fadd_rn(__fmul_rn(sx,sx), __fmul_rn(sy,sy)),
                         __fmul_rn(sz,sz));
    const float R2 = 0.2f * 0.2f;

    int cnt = 0;
    for (int base = 0; base < Npt; base += 32) {
        int   i = base + lane;
        float xx = p[i*3+0], yy = p[i*3+1], zz = p[i*3+2];
        float pn = __fadd_rn(__fadd_rn(__fmul_rn(xx,xx), __fmul_rn(yy,yy)),
                             __fmul_rn(zz,zz));
        float dot = __fadd_rn(__fadd_rn(__fmul_rn(sx,xx), __fmul_rn(sy,yy)),
                              __fmul_rn(sz,zz));
        float d2 = __fsub_rn(__fadd_rn(sn, pn), __fmul_rn(2.0f, dot));
        bool  in = (d2 <= R2);
        unsigned ball = __ballot_sync(0xffffffffu, in);
        if (in) {
            int ppos = cnt + __popc(ball & ((1u << lane) - 1u));
            if (ppos < Kn) g_nbr[cm * Kn + ppos] = i;
        }
        cnt += __popc(ball);
        if (cnt >= Kn) break;
    }
    if (cnt > Kn) cnt = Kn;
    for (int k = cnt + lane; k < Kn; k += 32) g_nbr[cm * Kn + k] = 0;
    if (lane == 0) g_cnt[cm] = cnt;
}

// ============================ 3) MLP (R16 exact) ===========================
#define PITCH 272
#define OFF_W1H 0
#define OFF_W1L 21760
#define OFF_W2H 43520
#define OFF_W2L 78336
#define OFF_FH  113152
#define OFF_FL  147968
#define OFF_B1  182784
#define OFF_B2  183296
#define OFF_WMX 183808
#define MLP_SMEM 187904

__device__ __forceinline__ uint32_t smem_u32(const void* p) {
    uint32_t a;
    asm("{ .reg .u64 t; cvta.to.shared.u64 t, %1; cvt.u32.u64 %0, t; }"
        : "=r"(a) : "l"(p));
    return a;
}
__device__ __forceinline__ void ldsm_x4(uint32_t addr, uint32_t* r) {
    asm volatile("ldmatrix.sync.aligned.m8n8.x4.shared.b16 {%0,%1,%2,%3}, [%4];"
        : "=r"(r[0]), "=r"(r[1]), "=r"(r[2]), "=r"(r[3]) : "r"(addr));
}
__device__ __forceinline__ void ldsm_x4t(uint32_t addr, uint32_t* r) {
    asm volatile("ldmatrix.sync.aligned.m8n8.x4.trans.shared.b16 {%0,%1,%2,%3}, [%4];"
        : "=r"(r[0]), "=r"(r[1]), "=r"(r[2]), "=r"(r[3]) : "r"(addr));
}
__device__ __forceinline__ void mma16816(float* d, const uint32_t* a, const uint32_t* b) {
    asm volatile("mma.sync.aligned.m16n8k16.row.col.f32.bf16.bf16.f32 "
        "{%0,%1,%2,%3}, {%4,%5,%6,%7}, {%8,%9}, {%0,%1,%2,%3};"
        : "+f"(d[0]), "+f"(d[1]), "+f"(d[2]), "+f"(d[3])
        : "r"(a[0]), "r"(a[1]), "r"(a[2]), "r"(a[3]), "r"(b[0]), "r"(b[1]));
}
__device__ __forceinline__ void pack_hilo(float v0, float v1, uint32_t& hi, uint32_t& lo) {
    uint32_t h;
    asm("cvt.rn.bf16x2.f32 %0, %1, %2;" : "=r"(h) : "f"(v1), "f"(v0));
    __nv_bfloat162 hh = *reinterpret_cast<__nv_bfloat162*>(&h);
    float e0 = v0 - __bfloat162float(hh.x);
    float e1 = v1 - __bfloat162float(hh.y);
    uint32_t l;
    asm("cvt.rn.bf16x2.f32 %0, %1, %2;" : "=r"(l) : "f"(e1), "f"(e0));
    hi = h; lo = l;
}

template <int KSTEPS>
__device__ __forceinline__ void do_layer(char* sm, int offAh, int offAl,
                                         int offBh, int offBl,
                                         int wrow0, int colbase,
                                         int lane, float d[8][4]) {
    uint32_t aHi = smem_u32(sm + offAh) + (uint32_t)(wrow0 + (lane & 15)) * PITCH
                   + ((lane >> 4) << 4);
    uint32_t aLo = smem_u32(sm + offAl) + (uint32_t)(wrow0 + (lane & 15)) * PITCH
                   + ((lane >> 4) << 4);
    uint32_t bprow = (uint32_t)((lane & 7) + ((lane >> 3) & 1) * 8) * PITCH
                     + (uint32_t)((lane >> 4) << 4) + (uint32_t)colbase * 2;
    uint32_t bHi0 = smem_u32(sm + offBh) + bprow;
    uint32_t bLo0 = smem_u32(sm + offBl) + bprow;
#pragma unroll
    for (int ks = 0; ks < KSTEPS; ks++) {
        uint32_t ah[4], al[4];
        ldsm_x4(aHi + ks * 32, ah);
        ldsm_x4(aLo + ks * 32, al);
        uint32_t bh_b = bHi0 + (uint32_t)ks * 16 * PITCH;
        uint32_t bl_b = bLo0 + (uint32_t)ks * 16 * PITCH;
#pragma unroll
        for (int ntp = 0; ntp < 4; ntp++) {
            uint32_t bh[4], bl[4];
            ldsm_x4t(bh_b + ntp * 32, bh);
            ldsm_x4t(bl_b + ntp * 32, bl);
            mma16816(d[2*ntp],     ah, bh);
            mma16816(d[2*ntp + 1], ah, bh + 2);
            mma16816(d[2*ntp],     ah, bl);
            mma16816(d[2*ntp + 1], ah, bl + 2);
            mma16816(d[2*ntp],     al, bh);
            mma16816(d[2*ntp + 1], al, bh + 2);
        }
    }
}

extern __shared__ __align__(128) char mlps[];

__global__ __launch_bounds__(512, 1) void mlp_kernel(
    const float* __restrict__ x, const float* __restrict__ pos,
    const float* __restrict__ W1, const float* __restrict__ b1,
    const float* __restrict__ W2, const float* __restrict__ b2,
    float* __restrict__ out) {
    char* sm = mlps;
    float* b1s = (float*)(sm + OFF_B1);
    float* b2s = (float*)(sm + OFF_B2);
    float* wmx = (float*)(sm + OFF_WMX);

    int tid = threadIdx.x, lane = tid & 31, warp = tid >> 5;
    int rw      = warp & 7;
    int half    = warp >> 3;
    int wrow0   = rw * 16;
    int colbase = half * 64;

    for (int i = tid; i < 80 * 128; i += 512) {
        int kk = i >> 7, n = i & 127;
        float v = (kk < CIN) ? W1[kk * Hd + n] : 0.f;
        __nv_bfloat16 hv = __float2bfloat16(v);
        *(__nv_bfloat16*)(sm + OFF_W1H + kk * PITCH + n * 2) = hv;
        *(__nv_bfloat16*)(sm + OFF_W1L + kk * PITCH + n * 2) =
            __float2bfloat16(v - __bfloat162float(hv));
    }
    for (int i = tid; i < 128 * 128; i += 512) {
        int kk = i >> 7, n = i & 127;
        float v = W2[kk * Hd + n];
        __nv_bfloat16 hv = __float2bfloat16(v);
        *(__nv_bfloat16*)(sm + OFF_W2H + kk * PITCH + n * 2) = hv;
        *(__nv_bfloat16*)(sm + OFF_W2L + kk * PITCH + n * 2) =
            __float2bfloat16(v - __bfloat162float(hv));
    }
    if (tid < Hd) { b1s[tid] = b1[tid]; b2s[tid] = b2[tid]; }
    __syncthreads();

    for (int bc = blockIdx.x * 2; bc < Bsz * Mc; bc += gridDim.x * 2) {
        int b = bc >> 10;

        {
            int r = tid >> 2, h = tid & 3;
            int cm = bc + (r >> 6);
            int k  = r & 63;
            int nb = __ldg(g_nbr + cm * Kn + k);
            const float* xr = x + ((size_t)b * Npt + nb) * Cft + h * 16;
            char* fh = sm + OFF_FH + r * PITCH + h * 32;
            char* fl = sm + OFF_FL + r * PITCH + h * 32;
#pragma unroll
            for (int j = 0; j < 4; j++) {
                float4 v = *(const float4*)(xr + j * 4);
                uint32_t h0, l0, h1v, l1v;
                pack_hilo(v.x, v.y, h0, l0);
                pack_hilo(v.z, v.w, h1v, l1v);
                *(uint32_t*)(fh + j * 8)     = h0;
                *(uint32_t*)(fh + j * 8 + 4) = h1v;
                *(uint32_t*)(fl + j * 8)     = l0;
                *(uint32_t*)(fl + j * 8 + 4) = l1v;
            }
            if (h == 0) {
                const float* pb = pos + b * Npt * 3;
                float pd0 = pb[nb*3+0] - g_ctr[cm*3+0];
                float pd1 = pb[nb*3+1] - g_ctr[cm*3+1];
                float pd2 = pb[nb*3+2] - g_ctr[cm*3+2];
                char* fh2 = sm + OFF_FH + r * PITCH + 128;
                char* fl2 = sm + OFF_FL + r * PITCH + 128;
                uint32_t h0, l0, h1v, l1v;
                pack_hilo(pd0, pd1, h0, l0);
                pack_hilo(pd2, 0.f, h1v, l1v);
                *(uint32_t*)(fh2)     = h0;  *(uint32_t*)(fh2 + 4) = h1v;
                *(uint32_t*)(fl2)     = l0;  *(uint32_t*)(fl2 + 4) = l1v;
#pragma unroll
                for (int j = 2; j < 8; j++) {
                    *(uint32_t*)(fh2 + j * 4) = 0u;
                    *(uint32_t*)(fl2 + j * 4) = 0u;
                }
            }
        }
        __syncthreads();

        float d[8][4];
#pragma unroll
        for (int nt = 0; nt < 8; nt++)
#pragma unroll
            for (int q = 0; q < 4; q++) d[nt][q] = 0.f;
        do_layer<5>(sm, OFF_FH, OFF_FL, OFF_W1H, OFF_W1L, wrow0, colbase, lane, d);

        {
            int r0 = wrow0 + (lane >> 2);
#pragma unroll
            for (int nt = 0; nt < 8; nt++) {
                int c0 = colbase + nt * 8 + (lane & 3) * 2;
                float v00 = fmaxf(d[nt][0] + b1s[c0],     0.f);
                float v01 = fmaxf(d[nt][1] + b1s[c0 + 1], 0.f);
                float v10 = fmaxf(d[nt][2] + b1s[c0],     0.f);
                float v11 = fmaxf(d[nt][3] + b1s[c0 + 1], 0.f);
                uint32_t h0, l0, h1v, l1v;
                pack_hilo(v00, v01, h0, l0);
                pack_hilo(v10, v11, h1v, l1v);
                *(uint32_t*)(sm + OFF_FH + r0 * PITCH + c0 * 2)       = h0;
                *(uint32_t*)(sm + OFF_FL + r0 * PITCH + c0 * 2)       = l0;
                *(uint32_t*)(sm + OFF_FH + (r0 + 8) * PITCH + c0 * 2) = h1v;
                *(uint32_t*)(sm + OFF_FL + (r0 + 8) * PITCH + c0 * 2) = l1v;
            }
        }
        __syncthreads();

#pragma unroll
        for (int nt = 0; nt < 8; nt++)
#pragma unroll
            for (int q = 0; q < 4; q++) d[nt][q] = 0.f;
        do_layer<8>(sm, OFF_FH, OFF_FL, OFF_W2H, OFF_W2L, wrow0, colbase, lane, d);

        {
            int cnt_w = __ldg(g_cnt + bc + (rw >> 2));
            int k0 = (wrow0 & 63) + (lane >> 2);
            bool va = k0 < cnt_w, vb = (k0 + 8) < cnt_w;
#pragma unroll
            for (int nt = 0; nt < 8; nt++) {
                int c0 = nt * 8 + (lane & 3) * 2;
                float m0 = fmaxf(va ? fmaxf(d[nt][0] + b2s[colbase + c0], 0.f) : 0.f,
                                 vb ? fmaxf(d[nt][2] + b2s[colbase + c0], 0.f) : 0.f);
                float m1 = fmaxf(va ? fmaxf(d[nt][1] + b2s[colbase + c0 + 1], 0.f) : 0.f,
                                 vb ? fmaxf(d[nt][3] + b2s[colbase + c0 + 1], 0.f) : 0.f);
#pragma unroll
                for (int o = 4; o <= 16; o <<= 1) {
                    m0 = fmaxf(m0, __shfl_xor_sync(0xffffffffu, m0, o));
                    m1 = fmaxf(m1, __shfl_xor_sync(0xffffffffu, m1, o));
                }
                if (lane < 4) {
                    wmx[warp * 64 + c0]     = m0;
                    wmx[warp * 64 + c0 + 1] = m1;
                }
            }
        }
        __syncthreads();
        if (tid < 256) {
            int col = tid & 127, ctr = tid >> 7;
            int hf = col >> 6, jj = col & 63;
            int base = (hf * 8 + ctr * 4) * 64 + jj;
            float mv = fmaxf(fmaxf(wmx[base], wmx[base + 64]),
                             fmaxf(wmx[base + 128], wmx[base + 192]));
            int cmo = bc + ctr;
            out[(size_t)cmo * Hd + col] = (__ldg(g_cnt + cmo) > 0) ? mv : 0.f;
        }
    }
}

// ============================ launch ======================================
extern "C" void kernel_launch(void* const* d_in, const int* in_sizes, int n_in,
                              void* d_out, int out_size) {
    const float* x   = (const float*)d_in[0];
    const float* pos = (const float*)d_in[1];
    const float* W1  = (const float*)d_in[2];
    const float* b1  = (const float*)d_in[3];
    const float* W2  = (const float*)d_in[4];
    const float* b2  = (const float*)d_in[5];
    float* out = (float*)d_out;

    float* poss;
    if (out_size >= Bsz * Mc * (Hd + 3)) {
        poss = out + (size_t)Bsz * Mc * Hd;
    } else {
        void* tmp = nullptr;
        cudaGetSymbolAddress(&tmp, g_poss_dump);
        poss = (float*)tmp;
    }

    cudaFuncSetAttribute(mlp_kernel, cudaFuncAttributeMaxDynamicSharedMemorySize,
                         MLP_SMEM);
    cudaFuncSetAttribute(fps_kernel, cudaFuncAttributeMaxDynamicSharedMemorySize,
                         Npt * 16);

    fps_kernel<<<Bsz, FPS_T, Npt * 16>>>(pos);
    query_kernel<<<(Bsz * Mc) / QWARPS, QWARPS * 32>>>(pos, poss);
    mlp_kernel<<<152, 512, MLP_SMEM>>>(x, pos, W1, b1, W2, b2, out);
}